// round 1
// baseline (speedup 1.0000x reference)
#include <cuda_runtime.h>
#include <cuda_bf16.h>
#include <math.h>

// Problem constants
#define S_LEN 2048
#define E_DIM 1024
#define NHEAD 16
#define HDIM  64
#define HD    1024   // NHEAD*HDIM

// Scratch (device globals; no cudaMalloc allowed)
__device__ float g_Q[S_LEN * HD];
__device__ float g_K[S_LEN * HD];
__device__ float g_V[S_LEN * HD];
__device__ float g_A[S_LEN * HD];

// ---------------------------------------------------------------------------
// NT SGEMM: C[M,N] = A[M,K] * B[N,K]^T, all row-major, M%128==0, N%64==0, K%16==0
// Block tile 128x64, thread tile 8x4, BK=16, 256 threads.
// ---------------------------------------------------------------------------
__global__ void __launch_bounds__(256, 2)
sgemm_nt(const float* __restrict__ A, const float* __restrict__ B,
         float* __restrict__ C, int M, int N, int K)
{
    __shared__ float As[16][128];
    __shared__ float Bs[16][64];

    const int tid = threadIdx.x;
    const int tx = tid & 15;        // 0..15 (cols)
    const int ty = tid >> 4;        // 0..15 (rows)
    const int m0 = blockIdx.y * 128;
    const int n0 = blockIdx.x * 64;

    float acc[8][4];
#pragma unroll
    for (int i = 0; i < 8; i++)
#pragma unroll
        for (int j = 0; j < 4; j++) acc[i][j] = 0.f;

    for (int k0 = 0; k0 < K; k0 += 16) {
        // Load A tile 128x16 (2 float4 per thread), store transposed
#pragma unroll
        for (int r = 0; r < 2; r++) {
            int idx = tid + r * 256;        // 0..511
            int row = idx >> 2;             // 0..127
            int kc  = (idx & 3) << 2;       // 0,4,8,12
            float4 a = *(const float4*)(A + (size_t)(m0 + row) * K + k0 + kc);
            As[kc + 0][row] = a.x;
            As[kc + 1][row] = a.y;
            As[kc + 2][row] = a.z;
            As[kc + 3][row] = a.w;
        }
        // Load B tile 64x16 (1 float4 per thread), store transposed
        {
            int row = tid >> 2;             // 0..63
            int kc  = (tid & 3) << 2;
            float4 b = *(const float4*)(B + (size_t)(n0 + row) * K + k0 + kc);
            Bs[kc + 0][row] = b.x;
            Bs[kc + 1][row] = b.y;
            Bs[kc + 2][row] = b.z;
            Bs[kc + 3][row] = b.w;
        }
        __syncthreads();

#pragma unroll
        for (int kk = 0; kk < 16; kk++) {
            float4 a0 = *(const float4*)(&As[kk][ty * 8]);
            float4 a1 = *(const float4*)(&As[kk][ty * 8 + 4]);
            float4 b0 = *(const float4*)(&Bs[kk][tx * 4]);
            float av[8] = {a0.x, a0.y, a0.z, a0.w, a1.x, a1.y, a1.z, a1.w};
            float bv[4] = {b0.x, b0.y, b0.z, b0.w};
#pragma unroll
            for (int i = 0; i < 8; i++)
#pragma unroll
                for (int j = 0; j < 4; j++)
                    acc[i][j] = fmaf(av[i], bv[j], acc[i][j]);
        }
        __syncthreads();
    }

#pragma unroll
    for (int i = 0; i < 8; i++) {
        float4 v = make_float4(acc[i][0], acc[i][1], acc[i][2], acc[i][3]);
        *(float4*)(C + (size_t)(m0 + ty * 8 + i) * N + n0 + tx * 4) = v;
    }
}

// ---------------------------------------------------------------------------
// Flash attention (fp32), per (query-tile, head) block.
// 64 queries x 64 keys per iteration, online softmax, 256 threads (16x16),
// each thread owns a 4x4 tile. Q/K stored transposed (d-major) in smem.
// ---------------------------------------------------------------------------
#define FA_STRIDE 68

__global__ void __launch_bounds__(256, 2)
flash_kernel(const float* __restrict__ Q, const float* __restrict__ K,
             const float* __restrict__ V, float* __restrict__ Aout)
{
    extern __shared__ float sm[];
    float* Qt = sm;                        // [64][68], Qt[d][r]
    float* Kt = Qt + 64 * FA_STRIDE;       // [64][68], Kt[d][c]
    float* Vs = Kt + 64 * FA_STRIDE;       // [64][68], Vs[k][d]
    float* Ps = Vs + 64 * FA_STRIDE;       // [64][68], Ps[r][k]

    const int tid = threadIdx.x;
    const int tx = tid & 15;
    const int ty = tid >> 4;
    const int h  = blockIdx.y;
    const int q0 = blockIdx.x * 64;
    const float scale = 0.125f;            // 1/sqrt(64)

    // Load Q tile, transposed + pre-scaled
#pragma unroll
    for (int it = 0; it < 4; it++) {
        int idx = tid + it * 256;          // 0..1023
        int r  = idx >> 4;                 // 0..63
        int dc = (idx & 15) << 2;          // 0..60 step 4
        float4 v = *(const float4*)(Q + (size_t)(q0 + r) * HD + h * HDIM + dc);
        Qt[(dc + 0) * FA_STRIDE + r] = v.x * scale;
        Qt[(dc + 1) * FA_STRIDE + r] = v.y * scale;
        Qt[(dc + 2) * FA_STRIDE + r] = v.z * scale;
        Qt[(dc + 3) * FA_STRIDE + r] = v.w * scale;
    }

    float m_i[4], l_i[4], o[4][4];
#pragma unroll
    for (int i = 0; i < 4; i++) {
        m_i[i] = -INFINITY;
        l_i[i] = 0.f;
#pragma unroll
        for (int j = 0; j < 4; j++) o[i][j] = 0.f;
    }

    for (int kt = 0; kt < S_LEN / 64; kt++) {
        const int k0 = kt * 64;
        __syncthreads();   // previous PV must finish before K/V overwrite
        // Load K (transposed) and V (natural)
#pragma unroll
        for (int it = 0; it < 4; it++) {
            int idx = tid + it * 256;
            int r  = idx >> 4;
            int dc = (idx & 15) << 2;
            float4 kv = *(const float4*)(K + (size_t)(k0 + r) * HD + h * HDIM + dc);
            Kt[(dc + 0) * FA_STRIDE + r] = kv.x;
            Kt[(dc + 1) * FA_STRIDE + r] = kv.y;
            Kt[(dc + 2) * FA_STRIDE + r] = kv.z;
            Kt[(dc + 3) * FA_STRIDE + r] = kv.w;
            float4 vv = *(const float4*)(V + (size_t)(k0 + r) * HD + h * HDIM + dc);
            *(float4*)(Vs + r * FA_STRIDE + dc) = vv;
        }
        __syncthreads();

        // Sc = (Q*scale) K^T : rows ty*4+i, cols tx*4+j
        float sc[4][4];
#pragma unroll
        for (int i = 0; i < 4; i++)
#pragma unroll
            for (int j = 0; j < 4; j++) sc[i][j] = 0.f;

#pragma unroll 8
        for (int d = 0; d < 64; d++) {
            float4 a = *(const float4*)(Qt + d * FA_STRIDE + ty * 4);
            float4 b = *(const float4*)(Kt + d * FA_STRIDE + tx * 4);
            float av[4] = {a.x, a.y, a.z, a.w};
            float bv[4] = {b.x, b.y, b.z, b.w};
#pragma unroll
            for (int i = 0; i < 4; i++)
#pragma unroll
                for (int j = 0; j < 4; j++)
                    sc[i][j] = fmaf(av[i], bv[j], sc[i][j]);
        }

        // Online softmax update per owned row
#pragma unroll
        for (int i = 0; i < 4; i++) {
            float mx = fmaxf(fmaxf(sc[i][0], sc[i][1]), fmaxf(sc[i][2], sc[i][3]));
#pragma unroll
            for (int off = 8; off >= 1; off >>= 1)
                mx = fmaxf(mx, __shfl_xor_sync(0xffffffffu, mx, off));
            float m_new = fmaxf(m_i[i], mx);
            float corr  = __expf(m_i[i] - m_new);
            float rs = 0.f;
#pragma unroll
            for (int j = 0; j < 4; j++) {
                float p = __expf(sc[i][j] - m_new);
                sc[i][j] = p;
                rs += p;
            }
#pragma unroll
            for (int off = 8; off >= 1; off >>= 1)
                rs += __shfl_xor_sync(0xffffffffu, rs, off);
            l_i[i] = l_i[i] * corr + rs;
            m_i[i] = m_new;
#pragma unroll
            for (int j = 0; j < 4; j++) o[i][j] *= corr;
            *(float4*)(Ps + (ty * 4 + i) * FA_STRIDE + tx * 4) =
                make_float4(sc[i][0], sc[i][1], sc[i][2], sc[i][3]);
        }
        __syncthreads();

        // O += P * V : o[i][j], d-col = tx*4+j
#pragma unroll 8
        for (int k = 0; k < 64; k++) {
            float4 vv = *(const float4*)(Vs + k * FA_STRIDE + tx * 4);
            float bv[4] = {vv.x, vv.y, vv.z, vv.w};
            float pv[4];
#pragma unroll
            for (int i = 0; i < 4; i++)
                pv[i] = Ps[(ty * 4 + i) * FA_STRIDE + k];
#pragma unroll
            for (int i = 0; i < 4; i++)
#pragma unroll
                for (int j = 0; j < 4; j++)
                    o[i][j] = fmaf(pv[i], bv[j], o[i][j]);
        }
    }

    // Epilogue: normalize, write to concat-head layout [S, H*DV]
#pragma unroll
    for (int i = 0; i < 4; i++) {
        float inv = 1.f / l_i[i];
        float4 v = make_float4(o[i][0] * inv, o[i][1] * inv,
                               o[i][2] * inv, o[i][3] * inv);
        *(float4*)(Aout + (size_t)(q0 + ty * 4 + i) * HD + h * HDIM + tx * 4) = v;
    }
}

// ---------------------------------------------------------------------------
// Launch
// ---------------------------------------------------------------------------
extern "C" void kernel_launch(void* const* d_in, const int* in_sizes, int n_in,
                              void* d_out, int out_size)
{
    (void)in_sizes; (void)n_in; (void)out_size;
    const float* x  = (const float*)d_in[0];
    const float* Wq = (const float*)d_in[1];
    const float* Wk = (const float*)d_in[2];
    const float* Wv = (const float*)d_in[3];
    const float* Wo = (const float*)d_in[4];
    float* out = (float*)d_out;

    float *dQ, *dK, *dV, *dA;
    cudaGetSymbolAddress((void**)&dQ, g_Q);
    cudaGetSymbolAddress((void**)&dK, g_K);
    cudaGetSymbolAddress((void**)&dV, g_V);
    cudaGetSymbolAddress((void**)&dA, g_A);

    dim3 gproj(HD / 64, S_LEN / 128);   // (16, 16)
    sgemm_nt<<<gproj, 256>>>(x, Wq, dQ, S_LEN, HD, E_DIM);
    sgemm_nt<<<gproj, 256>>>(x, Wk, dK, S_LEN, HD, E_DIM);
    sgemm_nt<<<gproj, 256>>>(x, Wv, dV, S_LEN, HD, E_DIM);

    size_t smem = 4 * 64 * FA_STRIDE * sizeof(float);  // 69632 B
    cudaFuncSetAttribute(flash_kernel,
                         cudaFuncAttributeMaxDynamicSharedMemorySize, (int)smem);
    flash_kernel<<<dim3(S_LEN / 64, NHEAD), 256, smem>>>(dQ, dK, dV, dA);

    sgemm_nt<<<gproj, 256>>>(dA, Wo, out, S_LEN, HD, HD);
}

// round 5
// speedup vs baseline: 2.9523x; 2.9523x over previous
#include <cuda_runtime.h>
#include <cuda_bf16.h>
#include <math.h>
#include <cstdint>

#define S_LEN 2048
#define HD    1024
#define ALPHA_Q 0.1803368801111601f   // 0.125 * log2(e)

// ---------------------------------------------------------------------------
// Scratch (device globals)
// ---------------------------------------------------------------------------
__device__ __align__(16) __nv_bfloat16 g_xh[S_LEN * HD],  g_xl[S_LEN * HD];
__device__ __align__(16) __nv_bfloat16 g_wqh[HD * HD],    g_wql[HD * HD];
__device__ __align__(16) __nv_bfloat16 g_wkh[HD * HD],    g_wkl[HD * HD];
__device__ __align__(16) __nv_bfloat16 g_wvh[HD * HD],    g_wvl[HD * HD];
__device__ __align__(16) __nv_bfloat16 g_woh[HD * HD],    g_wol[HD * HD];
__device__ __align__(16) __nv_bfloat16 g_Qh[S_LEN * HD],  g_Ql[S_LEN * HD];
__device__ __align__(16) __nv_bfloat16 g_Kh[S_LEN * HD],  g_Kl[S_LEN * HD];
__device__ __align__(16) __nv_bfloat16 g_Vh[S_LEN * HD],  g_Vl[S_LEN * HD];
__device__ __align__(16) __nv_bfloat16 g_Ah[S_LEN * HD],  g_Al[S_LEN * HD];

// ---------------------------------------------------------------------------
// Portable PTX helpers (sm_80-level, legal on bare sm_103)
// ---------------------------------------------------------------------------
__device__ __forceinline__ uint32_t smem_u32(const void* p) {
    uint32_t a;
    asm("{ .reg .u64 t; cvta.to.shared.u64 t, %1; cvt.u32.u64 %0, t; }"
        : "=r"(a) : "l"(p));
    return a;
}
__device__ __forceinline__ void cp_async16(uint32_t dst, const void* src) {
    asm volatile("cp.async.cg.shared.global [%0], [%1], 16;" :: "r"(dst), "l"(src));
}
__device__ __forceinline__ void cp_commit() {
    asm volatile("cp.async.commit_group;" ::: "memory");
}
template<int N> __device__ __forceinline__ void cp_wait() {
    asm volatile("cp.async.wait_group %0;" :: "n"(N) : "memory");
}
__device__ __forceinline__ void ldsm_x4(uint32_t* r, uint32_t a) {
    asm volatile("ldmatrix.sync.aligned.m8n8.x4.shared.b16 {%0,%1,%2,%3}, [%4];"
                 : "=r"(r[0]), "=r"(r[1]), "=r"(r[2]), "=r"(r[3]) : "r"(a));
}
__device__ __forceinline__ void ldsm_x4_t(uint32_t* r, uint32_t a) {
    asm volatile("ldmatrix.sync.aligned.m8n8.x4.trans.shared.b16 {%0,%1,%2,%3}, [%4];"
                 : "=r"(r[0]), "=r"(r[1]), "=r"(r[2]), "=r"(r[3]) : "r"(a));
}
__device__ __forceinline__ void mma_bf16(float* c, const uint32_t* a, const uint32_t* b) {
    asm volatile(
        "mma.sync.aligned.m16n8k16.row.col.f32.bf16.bf16.f32 "
        "{%0,%1,%2,%3}, {%4,%5,%6,%7}, {%8,%9}, {%0,%1,%2,%3};"
        : "+f"(c[0]), "+f"(c[1]), "+f"(c[2]), "+f"(c[3])
        : "r"(a[0]), "r"(a[1]), "r"(a[2]), "r"(a[3]), "r"(b[0]), "r"(b[1]));
}
__device__ __forceinline__ float ex2(float x) {
    float r; asm("ex2.approx.f32 %0, %1;" : "=f"(r) : "f"(x)); return r;
}
// 128B-row swizzle; cb must be 16B aligned
__device__ __forceinline__ uint32_t swz(int row, int cb) {
    return (uint32_t)(row * 128 + (cb ^ ((row & 7) << 4)));
}
// two floats -> packed bf16x2 hi + bf16x2 lo (round-to-nearest split)
__device__ __forceinline__ void split2(float x, float y, uint32_t& hi, uint32_t& lo) {
    __nv_bfloat16 hx = __float2bfloat16(x), hy = __float2bfloat16(y);
    hi = (uint32_t)(*(uint16_t*)&hx) | ((uint32_t)(*(uint16_t*)&hy) << 16);
    float rx = x - __bfloat162float(hx), ry = y - __bfloat162float(hy);
    __nv_bfloat16 lx = __float2bfloat16(rx), ly = __float2bfloat16(ry);
    lo = (uint32_t)(*(uint16_t*)&lx) | ((uint32_t)(*(uint16_t*)&ly) << 16);
}

// ---------------------------------------------------------------------------
// fp32 -> (bf16 hi, bf16 lo)
// ---------------------------------------------------------------------------
__global__ void split_kernel(const float* __restrict__ in,
                             __nv_bfloat16* __restrict__ hi,
                             __nv_bfloat16* __restrict__ lo, int n4)
{
    int i = blockIdx.x * blockDim.x + threadIdx.x;
    if (i >= n4) return;
    float4 v = ((const float4*)in)[i];
    uint32_t h0, l0, h1, l1;
    split2(v.x, v.y, h0, l0);
    split2(v.z, v.w, h1, l1);
    ((uint32_t*)hi)[2 * i + 0] = h0;
    ((uint32_t*)hi)[2 * i + 1] = h1;
    ((uint32_t*)lo)[2 * i + 0] = l0;
    ((uint32_t*)lo)[2 * i + 1] = l1;
}

// ---------------------------------------------------------------------------
// Split-GEMM:  C[2048,1024] = sum over 3 sections of Asec[2048,1024]*Bsec[1024,1024]^T
// sections: (Ahi,Bhi), (Alo,Bhi), (Ahi,Blo).  Block 128x128, BK=64, 8 warps,
// double-buffered cp.async.  Epilogue: *alpha, optional fp32 and bf16 hi/lo out.
// ---------------------------------------------------------------------------
#define G_STAGE 32768
#define GEMM_SMEM (2 * G_STAGE)

__global__ void __launch_bounds__(256)
gemm_split(const __nv_bfloat16* __restrict__ A0, const __nv_bfloat16* __restrict__ A1,
           const __nv_bfloat16* __restrict__ A2, const __nv_bfloat16* __restrict__ B0,
           const __nv_bfloat16* __restrict__ B1, const __nv_bfloat16* __restrict__ B2,
           __nv_bfloat16* __restrict__ outHi, __nv_bfloat16* __restrict__ outLo,
           float* __restrict__ outF, float alpha)
{
    extern __shared__ __align__(128) char sm_g[];
    const uint32_t sb = smem_u32(sm_g);
    const int tid = threadIdx.x;
    const int lane = tid & 31, wid = tid >> 5;
    const int wm = wid & 3, wn = wid >> 2;
    const int m0 = blockIdx.y * 128, n0 = blockIdx.x * 128;

    const __nv_bfloat16* Asec[3] = {A0, A1, A2};
    const __nv_bfloat16* Bsec[3] = {B0, B1, B2};

    float c[2][8][4];
#pragma unroll
    for (int mt = 0; mt < 2; mt++)
#pragma unroll
        for (int nt = 0; nt < 8; nt++)
#pragma unroll
            for (int j = 0; j < 4; j++) c[mt][nt][j] = 0.f;

    auto issue = [&](int ck, int stage) {
        int sec = ck >> 4;
        size_t ko = (size_t)(ck & 15) * 128;
        const char* Ab = (const char*)Asec[sec];
        const char* Bb = (const char*)Bsec[sec];
        uint32_t dA = sb + stage * G_STAGE;
        uint32_t dB = dA + 16384;
#pragma unroll
        for (int i = 0; i < 4; i++) {
            int lin = tid + i * 256;
            int row = lin >> 3, cb = (lin & 7) << 4;
            cp_async16(dA + swz(row, cb), Ab + (size_t)(m0 + row) * 2048 + ko + cb);
            cp_async16(dB + swz(row, cb), Bb + (size_t)(n0 + row) * 2048 + ko + cb);
        }
        cp_commit();
    };

    issue(0, 0);
    issue(1, 1);

    for (int ck = 0; ck < 48; ck++) {
        if (ck == 47) cp_wait<0>(); else cp_wait<1>();
        __syncthreads();
        uint32_t aB = sb + (ck & 1) * G_STAGE;
        uint32_t bB = aB + 16384;
#pragma unroll
        for (int kk = 0; kk < 4; kk++) {
            uint32_t afr[2][4], bfr[8][2];
#pragma unroll
            for (int mt = 0; mt < 2; mt++) {
                int row = wm * 32 + mt * 16 + (lane & 15);
                int cb = kk * 32 + ((lane & 16) ? 16 : 0);
                ldsm_x4(afr[mt], aB + swz(row, cb));
            }
#pragma unroll
            for (int ng = 0; ng < 4; ng++) {
                uint32_t t[4];
                int row = wn * 64 + ng * 16 + (lane & 7) + ((lane & 16) ? 8 : 0);
                int cb = kk * 32 + ((lane & 8) ? 16 : 0);
                ldsm_x4(t, bB + swz(row, cb));
                bfr[2 * ng][0] = t[0];     bfr[2 * ng][1] = t[1];
                bfr[2 * ng + 1][0] = t[2]; bfr[2 * ng + 1][1] = t[3];
            }
#pragma unroll
            for (int mt = 0; mt < 2; mt++)
#pragma unroll
                for (int nt = 0; nt < 8; nt++)
                    mma_bf16(c[mt][nt], afr[mt], bfr[nt]);
        }
        __syncthreads();
        if (ck + 2 < 48) issue(ck + 2, ck & 1);
    }

    const int gid = lane >> 2, t2 = (lane & 3) * 2;
#pragma unroll
    for (int mt = 0; mt < 2; mt++)
#pragma unroll
        for (int hh = 0; hh < 2; hh++) {
            int row = m0 + wm * 32 + mt * 16 + gid + hh * 8;
#pragma unroll
            for (int nt = 0; nt < 8; nt++) {
                int col = n0 + wn * 64 + nt * 8 + t2;
                float v0 = c[mt][nt][2 * hh] * alpha;
                float v1 = c[mt][nt][2 * hh + 1] * alpha;
                size_t idx = (size_t)row * 1024 + col;
                if (outF) *(float2*)(outF + idx) = make_float2(v0, v1);
                if (outHi) {
                    uint32_t hb, lb;
                    split2(v0, v1, hb, lb);
                    ((uint32_t*)outHi)[idx >> 1] = hb;
                    ((uint32_t*)outLo)[idx >> 1] = lb;
                }
            }
        }
}

// ---------------------------------------------------------------------------
// Flash attention, bf16-split mma.sync. 256 threads = 8 warps, each warp 16 q
// rows; CTA = 128 q rows x 1 head; key tile 64. Q pre-scaled by 0.125*log2e.
// S = Qh*Kh + Ql*Kh + Qh*Kl ; P = exp2(S - m) ; O += Ph*Vh + Pl*Vh + Ph*Vl.
// ---------------------------------------------------------------------------
#define SQH 0
#define SQL 16384
#define SKH 32768
#define SKL 40960
#define SVH 49152
#define SVL 57344
#define FLASH_SMEM 65536

__global__ void __launch_bounds__(256)
flash_mma(const __nv_bfloat16* __restrict__ Qh_, const __nv_bfloat16* __restrict__ Ql_,
          const __nv_bfloat16* __restrict__ Kh_, const __nv_bfloat16* __restrict__ Kl_,
          const __nv_bfloat16* __restrict__ Vh_, const __nv_bfloat16* __restrict__ Vl_,
          __nv_bfloat16* __restrict__ Ah_, __nv_bfloat16* __restrict__ Al_)
{
    extern __shared__ __align__(128) char sm_f[];
    const uint32_t sb = smem_u32(sm_f);
    const int tid = threadIdx.x, lane = tid & 31, w = tid >> 5;
    const int h = blockIdx.y, q0 = blockIdx.x * 128;

    auto ldKV = [&](int kt) {
        size_t kr = (size_t)kt * 64;
#pragma unroll
        for (int i = 0; i < 2; i++) {
            int lin = tid + i * 256;            // 0..511
            int row = lin >> 3, cb = (lin & 7) << 4;
            size_t go = (kr + row) * 2048 + (size_t)h * 128 + cb;
            uint32_t so = swz(row, cb);
            cp_async16(sb + SKH + so, (const char*)Kh_ + go);
            cp_async16(sb + SKL + so, (const char*)Kl_ + go);
            cp_async16(sb + SVH + so, (const char*)Vh_ + go);
            cp_async16(sb + SVL + so, (const char*)Vl_ + go);
        }
        cp_commit();
    };

    // Q tile: 128 rows x 128B, hi + lo
#pragma unroll
    for (int i = 0; i < 4; i++) {
        int lin = tid + i * 256;                // 0..1023
        int row = lin >> 3, cb = (lin & 7) << 4;
        size_t go = (size_t)(q0 + row) * 2048 + (size_t)h * 128 + cb;
        cp_async16(sb + SQH + swz(row, cb), (const char*)Qh_ + go);
        cp_async16(sb + SQL + swz(row, cb), (const char*)Ql_ + go);
    }
    cp_commit();
    ldKV(0);
    cp_wait<1>();
    __syncthreads();

    // Persistent Q fragments (hi and lo)
    uint32_t qh[4][4], ql[4][4];
    {
        int row = w * 16 + (lane & 15);
#pragma unroll
        for (int kk = 0; kk < 4; kk++) {
            int cb = kk * 32 + ((lane & 16) ? 16 : 0);
            ldsm_x4(qh[kk], sb + SQH + swz(row, cb));
            ldsm_x4(ql[kk], sb + SQL + swz(row, cb));
        }
    }

    float m0v = -INFINITY, m1v = -INFINITY, l0v = 0.f, l1v = 0.f;
    float o[8][4];
#pragma unroll
    for (int d = 0; d < 8; d++)
#pragma unroll
        for (int j = 0; j < 4; j++) o[d][j] = 0.f;

    for (int kt = 0; kt < 32; kt++) {
        cp_wait<0>();
        __syncthreads();

        // ---- S = Q K^T (3-term split), 64 keys ----
        float c[8][4];
#pragma unroll
        for (int nt = 0; nt < 8; nt++)
#pragma unroll
            for (int j = 0; j < 4; j++) c[nt][j] = 0.f;

#pragma unroll
        for (int kk = 0; kk < 4; kk++) {
#pragma unroll
            for (int ng = 0; ng < 4; ng++) {
                uint32_t bh[4], bl[4];
                int row = ng * 16 + (lane & 7) + ((lane & 16) ? 8 : 0);
                int cb = kk * 32 + ((lane & 8) ? 16 : 0);
                ldsm_x4(bh, sb + SKH + swz(row, cb));
                ldsm_x4(bl, sb + SKL + swz(row, cb));
                mma_bf16(c[2 * ng],     qh[kk], bh);
                mma_bf16(c[2 * ng],     ql[kk], bh);
                mma_bf16(c[2 * ng],     qh[kk], bl);
                mma_bf16(c[2 * ng + 1], qh[kk], bh + 2);
                mma_bf16(c[2 * ng + 1], ql[kk], bh + 2);
                mma_bf16(c[2 * ng + 1], qh[kk], bl + 2);
            }
        }

        // ---- online softmax (2 rows per lane: gid and gid+8) ----
        float mx0 = -INFINITY, mx1 = -INFINITY;
#pragma unroll
        for (int nt = 0; nt < 8; nt++) {
            mx0 = fmaxf(mx0, fmaxf(c[nt][0], c[nt][1]));
            mx1 = fmaxf(mx1, fmaxf(c[nt][2], c[nt][3]));
        }
        mx0 = fmaxf(mx0, __shfl_xor_sync(0xffffffffu, mx0, 1));
        mx0 = fmaxf(mx0, __shfl_xor_sync(0xffffffffu, mx0, 2));
        mx1 = fmaxf(mx1, __shfl_xor_sync(0xffffffffu, mx1, 1));
        mx1 = fmaxf(mx1, __shfl_xor_sync(0xffffffffu, mx1, 2));
        float mn0 = fmaxf(m0v, mx0), mn1 = fmaxf(m1v, mx1);
        float cor0 = ex2(m0v - mn0), cor1 = ex2(m1v - mn1);
        float rs0 = 0.f, rs1 = 0.f;
#pragma unroll
        for (int nt = 0; nt < 8; nt++) {
            c[nt][0] = ex2(c[nt][0] - mn0);
            c[nt][1] = ex2(c[nt][1] - mn0);
            c[nt][2] = ex2(c[nt][2] - mn1);
            c[nt][3] = ex2(c[nt][3] - mn1);
            rs0 += c[nt][0] + c[nt][1];
            rs1 += c[nt][2] + c[nt][3];
        }
        rs0 += __shfl_xor_sync(0xffffffffu, rs0, 1);
        rs0 += __shfl_xor_sync(0xffffffffu, rs0, 2);
        rs1 += __shfl_xor_sync(0xffffffffu, rs1, 1);
        rs1 += __shfl_xor_sync(0xffffffffu, rs1, 2);
        l0v = l0v * cor0 + rs0;
        l1v = l1v * cor1 + rs1;
        m0v = mn0; m1v = mn1;
#pragma unroll
        for (int d = 0; d < 8; d++) {
            o[d][0] *= cor0; o[d][1] *= cor0;
            o[d][2] *= cor1; o[d][3] *= cor1;
        }

        // ---- O += P V (3-term split), V via ldmatrix.trans ----
#pragma unroll
        for (int kk = 0; kk < 4; kk++) {
            uint32_t ah[4], al[4];
            split2(c[2 * kk][0],     c[2 * kk][1],     ah[0], al[0]);
            split2(c[2 * kk][2],     c[2 * kk][3],     ah[1], al[1]);
            split2(c[2 * kk + 1][0], c[2 * kk + 1][1], ah[2], al[2]);
            split2(c[2 * kk + 1][2], c[2 * kk + 1][3], ah[3], al[3]);
            int row = kk * 16 + (lane & 15);
#pragma unroll
            for (int dg = 0; dg < 4; dg++) {
                uint32_t bh[4], bl[4];
                int cb = dg * 32 + ((lane & 16) ? 16 : 0);
                ldsm_x4_t(bh, sb + SVH + swz(row, cb));
                ldsm_x4_t(bl, sb + SVL + swz(row, cb));
                mma_bf16(o[2 * dg],     ah, bh);
                mma_bf16(o[2 * dg],     al, bh);
                mma_bf16(o[2 * dg],     ah, bl);
                mma_bf16(o[2 * dg + 1], ah, bh + 2);
                mma_bf16(o[2 * dg + 1], al, bh + 2);
                mma_bf16(o[2 * dg + 1], ah, bl + 2);
            }
        }
        __syncthreads();
        if (kt + 1 < 32) ldKV(kt + 1);
    }

    // ---- epilogue: normalize, split to bf16 hi/lo, concat-head layout ----
    float inv0 = 1.f / l0v, inv1 = 1.f / l1v;
    const int gid = lane >> 2, t2 = (lane & 3) * 2;
    int r0 = q0 + w * 16 + gid;
#pragma unroll
    for (int d = 0; d < 8; d++) {
        int col = h * 64 + d * 8 + t2;
        uint32_t hb, lb;
        size_t i0 = ((size_t)r0 * 1024 + col) >> 1;
        split2(o[d][0] * inv0, o[d][1] * inv0, hb, lb);
        ((uint32_t*)Ah_)[i0] = hb;
        ((uint32_t*)Al_)[i0] = lb;
        size_t i1 = ((size_t)(r0 + 8) * 1024 + col) >> 1;
        split2(o[d][2] * inv1, o[d][3] * inv1, hb, lb);
        ((uint32_t*)Ah_)[i1] = hb;
        ((uint32_t*)Al_)[i1] = lb;
    }
}

// ---------------------------------------------------------------------------
// Launch
// ---------------------------------------------------------------------------
extern "C" void kernel_launch(void* const* d_in, const int* in_sizes, int n_in,
                              void* d_out, int out_size)
{
    (void)in_sizes; (void)n_in; (void)out_size;
    const float* x  = (const float*)d_in[0];
    const float* Wq = (const float*)d_in[1];
    const float* Wk = (const float*)d_in[2];
    const float* Wv = (const float*)d_in[3];
    const float* Wo = (const float*)d_in[4];
    float* out = (float*)d_out;

    __nv_bfloat16 *xh, *xl, *qwh, *qwl, *kwh, *kwl, *vwh, *vwl, *owh, *owl;
    __nv_bfloat16 *Qh, *Ql, *Kh, *Kl, *Vh, *Vl, *Ah, *Al;
    cudaGetSymbolAddress((void**)&xh,  g_xh);  cudaGetSymbolAddress((void**)&xl,  g_xl);
    cudaGetSymbolAddress((void**)&qwh, g_wqh); cudaGetSymbolAddress((void**)&qwl, g_wql);
    cudaGetSymbolAddress((void**)&kwh, g_wkh); cudaGetSymbolAddress((void**)&kwl, g_wkl);
    cudaGetSymbolAddress((void**)&vwh, g_wvh); cudaGetSymbolAddress((void**)&vwl, g_wvl);
    cudaGetSymbolAddress((void**)&owh, g_woh); cudaGetSymbolAddress((void**)&owl, g_wol);
    cudaGetSymbolAddress((void**)&Qh,  g_Qh);  cudaGetSymbolAddress((void**)&Ql,  g_Ql);
    cudaGetSymbolAddress((void**)&Kh,  g_Kh);  cudaGetSymbolAddress((void**)&Kl,  g_Kl);
    cudaGetSymbolAddress((void**)&Vh,  g_Vh);  cudaGetSymbolAddress((void**)&Vl,  g_Vl);
    cudaGetSymbolAddress((void**)&Ah,  g_Ah);  cudaGetSymbolAddress((void**)&Al,  g_Al);

    cudaFuncSetAttribute(gemm_split, cudaFuncAttributeMaxDynamicSharedMemorySize, GEMM_SMEM);
    cudaFuncSetAttribute(flash_mma,  cudaFuncAttributeMaxDynamicSharedMemorySize, FLASH_SMEM);

    int n4x = S_LEN * HD / 4, n4w = HD * HD / 4;
    split_kernel<<<(n4x + 255) / 256, 256>>>(x,  xh,  xl,  n4x);
    split_kernel<<<(n4w + 255) / 256, 256>>>(Wq, qwh, qwl, n4w);
    split_kernel<<<(n4w + 255) / 256, 256>>>(Wk, kwh, kwl, n4w);
    split_kernel<<<(n4w + 255) / 256, 256>>>(Wv, vwh, vwl, n4w);
    split_kernel<<<(n4w + 255) / 256, 256>>>(Wo, owh, owl, n4w);

    dim3 gg(HD / 128, S_LEN / 128);   // (8, 16)
    gemm_split<<<gg, 256, GEMM_SMEM>>>(xh, xl, xh, qwh, qwh, qwl, Qh, Ql, nullptr,
                                       (float)ALPHA_Q);
    gemm_split<<<gg, 256, GEMM_SMEM>>>(xh, xl, xh, kwh, kwh, kwl, Kh, Kl, nullptr, 1.0f);
    gemm_split<<<gg, 256, GEMM_SMEM>>>(xh, xl, xh, vwh, vwh, vwl, Vh, Vl, nullptr, 1.0f);

    flash_mma<<<dim3(S_LEN / 128, 16), 256, FLASH_SMEM>>>(Qh, Ql, Kh, Kl, Vh, Vl, Ah, Al);

    gemm_split<<<gg, 256, GEMM_SMEM>>>(Ah, Al, Ah, owh, owh, owl, nullptr, nullptr, out, 1.0f);
}

// round 7
// speedup vs baseline: 3.1242x; 1.0582x over previous
#include <cuda_runtime.h>
#include <cuda_bf16.h>
#include <math.h>
#include <cstdint>

#define S_LEN 2048
#define HD    1024
#define ALPHA_Q 0.1803368801111601f   // 0.125 * log2(e)

// ---------------------------------------------------------------------------
// Scratch (device globals)
// ---------------------------------------------------------------------------
__device__ __align__(16) __nv_bfloat16 g_xh[S_LEN * HD],  g_xl[S_LEN * HD];
__device__ __align__(16) __nv_bfloat16 g_wqh[HD * HD],    g_wql[HD * HD];
__device__ __align__(16) __nv_bfloat16 g_wkh[HD * HD],    g_wkl[HD * HD];
__device__ __align__(16) __nv_bfloat16 g_wvh[HD * HD],    g_wvl[HD * HD];
__device__ __align__(16) __nv_bfloat16 g_woh[HD * HD],    g_wol[HD * HD];
__device__ __align__(16) __nv_bfloat16 g_Qh[S_LEN * HD],  g_Ql[S_LEN * HD];
__device__ __align__(16) __nv_bfloat16 g_Kh[S_LEN * HD],  g_Kl[S_LEN * HD];
__device__ __align__(16) __nv_bfloat16 g_Vh[S_LEN * HD],  g_Vl[S_LEN * HD];
__device__ __align__(16) __nv_bfloat16 g_Ah[S_LEN * HD],  g_Al[S_LEN * HD];

// ---------------------------------------------------------------------------
// Portable PTX helpers (sm_80-level, legal on bare sm_103)
// ---------------------------------------------------------------------------
__device__ __forceinline__ uint32_t smem_u32(const void* p) {
    uint32_t a;
    asm("{ .reg .u64 t; cvta.to.shared.u64 t, %1; cvt.u32.u64 %0, t; }"
        : "=r"(a) : "l"(p));
    return a;
}
__device__ __forceinline__ void cp_async16(uint32_t dst, const void* src) {
    asm volatile("cp.async.cg.shared.global [%0], [%1], 16;" :: "r"(dst), "l"(src));
}
__device__ __forceinline__ void cp_commit() {
    asm volatile("cp.async.commit_group;" ::: "memory");
}
template<int N> __device__ __forceinline__ void cp_wait() {
    asm volatile("cp.async.wait_group %0;" :: "n"(N) : "memory");
}
__device__ __forceinline__ void ldsm_x4(uint32_t* r, uint32_t a) {
    asm volatile("ldmatrix.sync.aligned.m8n8.x4.shared.b16 {%0,%1,%2,%3}, [%4];"
                 : "=r"(r[0]), "=r"(r[1]), "=r"(r[2]), "=r"(r[3]) : "r"(a));
}
__device__ __forceinline__ void ldsm_x4_t(uint32_t* r, uint32_t a) {
    asm volatile("ldmatrix.sync.aligned.m8n8.x4.trans.shared.b16 {%0,%1,%2,%3}, [%4];"
                 : "=r"(r[0]), "=r"(r[1]), "=r"(r[2]), "=r"(r[3]) : "r"(a));
}
__device__ __forceinline__ void mma_bf16(float* c, const uint32_t* a, const uint32_t* b) {
    asm volatile(
        "mma.sync.aligned.m16n8k16.row.col.f32.bf16.bf16.f32 "
        "{%0,%1,%2,%3}, {%4,%5,%6,%7}, {%8,%9}, {%0,%1,%2,%3};"
        : "+f"(c[0]), "+f"(c[1]), "+f"(c[2]), "+f"(c[3])
        : "r"(a[0]), "r"(a[1]), "r"(a[2]), "r"(a[3]), "r"(b[0]), "r"(b[1]));
}
__device__ __forceinline__ float ex2(float x) {
    float r; asm("ex2.approx.f32 %0, %1;" : "=f"(r) : "f"(x)); return r;
}
// 128B-row swizzle; cb must be 16B aligned
__device__ __forceinline__ uint32_t swz(int row, int cb) {
    return (uint32_t)(row * 128 + (cb ^ ((row & 7) << 4)));
}
// two floats -> packed bf16x2 hi + bf16x2 lo (round-to-nearest split)
__device__ __forceinline__ void split2(float x, float y, uint32_t& hi, uint32_t& lo) {
    __nv_bfloat16 hx = __float2bfloat16(x), hy = __float2bfloat16(y);
    hi = (uint32_t)(*(uint16_t*)&hx) | ((uint32_t)(*(uint16_t*)&hy) << 16);
    float rx = x - __bfloat162float(hx), ry = y - __bfloat162float(hy);
    __nv_bfloat16 lx = __float2bfloat16(rx), ly = __float2bfloat16(ry);
    lo = (uint32_t)(*(uint16_t*)&lx) | ((uint32_t)(*(uint16_t*)&ly) << 16);
}

// ---------------------------------------------------------------------------
// Fused fp32 -> (bf16 hi, bf16 lo) over x, Wq, Wk, Wv, Wo in ONE launch.
// Segment sizes in float4 units: x=524288, each W=262144; total 1572864.
// ---------------------------------------------------------------------------
#define N4_X 524288
#define N4_W 262144
#define N4_TOTAL (N4_X + 4 * N4_W)

__global__ void __launch_bounds__(256)
split_all(const float* __restrict__ x,  const float* __restrict__ Wq,
          const float* __restrict__ Wk, const float* __restrict__ Wv,
          const float* __restrict__ Wo)
{
    int i = blockIdx.x * blockDim.x + threadIdx.x;
    if (i >= N4_TOTAL) return;
    const float* in;
    __nv_bfloat16 *hi, *lo;
    int j = i;
    if (j < N4_X) {
        in = x;  hi = g_xh; lo = g_xl;
    } else if ((j -= N4_X) < N4_W) {
        in = Wq; hi = g_wqh; lo = g_wql;
    } else if ((j -= N4_W) < N4_W) {
        in = Wk; hi = g_wkh; lo = g_wkl;
    } else if ((j -= N4_W) < N4_W) {
        in = Wv; hi = g_wvh; lo = g_wvl;
    } else {
        j -= N4_W;
        in = Wo; hi = g_woh; lo = g_wol;
    }
    float4 v = ((const float4*)in)[j];
    uint32_t h0, l0, h1, l1;
    split2(v.x, v.y, h0, l0);
    split2(v.z, v.w, h1, l1);
    ((uint32_t*)hi)[2 * j + 0] = h0;
    ((uint32_t*)hi)[2 * j + 1] = h1;
    ((uint32_t*)lo)[2 * j + 0] = l0;
    ((uint32_t*)lo)[2 * j + 1] = l1;
}

// ---------------------------------------------------------------------------
// Split-GEMM core (device inline): C[2048,1024] = 3-section bf16-split NT GEMM.
// Block 128x128, BK=64, 8 warps, double-buffered cp.async.
// ---------------------------------------------------------------------------
#define G_STAGE 32768
#define GEMM_SMEM (2 * G_STAGE)

__device__ __forceinline__ void gemm_core(
    uint32_t sb,
    const __nv_bfloat16* Ahi, const __nv_bfloat16* Alo,
    const __nv_bfloat16* Bhi, const __nv_bfloat16* Blo,
    __nv_bfloat16* outHi, __nv_bfloat16* outLo, float* outF,
    float alpha, int m0, int n0)
{
    const int tid = threadIdx.x;
    const int lane = tid & 31, wid = tid >> 5;
    const int wm = wid & 3, wn = wid >> 2;

    const __nv_bfloat16* Asec[3] = {Ahi, Alo, Ahi};
    const __nv_bfloat16* Bsec[3] = {Bhi, Bhi, Blo};

    float c[2][8][4];
#pragma unroll
    for (int mt = 0; mt < 2; mt++)
#pragma unroll
        for (int nt = 0; nt < 8; nt++)
#pragma unroll
            for (int j = 0; j < 4; j++) c[mt][nt][j] = 0.f;

    auto issue = [&](int ck, int stage) {
        int sec = ck >> 4;
        size_t ko = (size_t)(ck & 15) * 128;
        const char* Ab = (const char*)Asec[sec];
        const char* Bb = (const char*)Bsec[sec];
        uint32_t dA = sb + stage * G_STAGE;
        uint32_t dB = dA + 16384;
#pragma unroll
        for (int i = 0; i < 4; i++) {
            int lin = tid + i * 256;
            int row = lin >> 3, cb = (lin & 7) << 4;
            cp_async16(dA + swz(row, cb), Ab + (size_t)(m0 + row) * 2048 + ko + cb);
            cp_async16(dB + swz(row, cb), Bb + (size_t)(n0 + row) * 2048 + ko + cb);
        }
        cp_commit();
    };

    issue(0, 0);
    issue(1, 1);

    for (int ck = 0; ck < 48; ck++) {
        if (ck == 47) cp_wait<0>(); else cp_wait<1>();
        __syncthreads();
        uint32_t aB = sb + (ck & 1) * G_STAGE;
        uint32_t bB = aB + 16384;
#pragma unroll
        for (int kk = 0; kk < 4; kk++) {
            uint32_t afr[2][4], bfr[8][2];
#pragma unroll
            for (int mt = 0; mt < 2; mt++) {
                int row = wm * 32 + mt * 16 + (lane & 15);
                int cb = kk * 32 + ((lane & 16) ? 16 : 0);
                ldsm_x4(afr[mt], aB + swz(row, cb));
            }
#pragma unroll
            for (int ng = 0; ng < 4; ng++) {
                uint32_t t[4];
                int row = wn * 64 + ng * 16 + (lane & 7) + ((lane & 16) ? 8 : 0);
                int cb = kk * 32 + ((lane & 8) ? 16 : 0);
                ldsm_x4(t, bB + swz(row, cb));
                bfr[2 * ng][0] = t[0];     bfr[2 * ng][1] = t[1];
                bfr[2 * ng + 1][0] = t[2]; bfr[2 * ng + 1][1] = t[3];
            }
#pragma unroll
            for (int mt = 0; mt < 2; mt++)
#pragma unroll
                for (int nt = 0; nt < 8; nt++)
                    mma_bf16(c[mt][nt], afr[mt], bfr[nt]);
        }
        __syncthreads();
        if (ck + 2 < 48) issue(ck + 2, ck & 1);
    }

    const int gid = lane >> 2, t2 = (lane & 3) * 2;
#pragma unroll
    for (int mt = 0; mt < 2; mt++)
#pragma unroll
        for (int hh = 0; hh < 2; hh++) {
            int row = m0 + wm * 32 + mt * 16 + gid + hh * 8;
#pragma unroll
            for (int nt = 0; nt < 8; nt++) {
                int col = n0 + wn * 64 + nt * 8 + t2;
                float v0 = c[mt][nt][2 * hh] * alpha;
                float v1 = c[mt][nt][2 * hh + 1] * alpha;
                size_t idx = (size_t)row * 1024 + col;
                if (outF) *(float2*)(outF + idx) = make_float2(v0, v1);
                if (outHi) {
                    uint32_t hb, lb;
                    split2(v0, v1, hb, lb);
                    ((uint32_t*)outHi)[idx >> 1] = hb;
                    ((uint32_t*)outLo)[idx >> 1] = lb;
                }
            }
        }
}

// Fused Q/K/V projections: blockIdx.z selects weight + destination.
__global__ void __launch_bounds__(256)
gemm_qkv()
{
    extern __shared__ __align__(128) char sm_g[];
    const uint32_t sb = smem_u32(sm_g);
    const int m0 = blockIdx.y * 128, n0 = blockIdx.x * 128;
    const int z = blockIdx.z;
    const __nv_bfloat16* Bh = (z == 0) ? g_wqh : (z == 1) ? g_wkh : g_wvh;
    const __nv_bfloat16* Bl = (z == 0) ? g_wql : (z == 1) ? g_wkl : g_wvl;
    __nv_bfloat16* oH = (z == 0) ? g_Qh : (z == 1) ? g_Kh : g_Vh;
    __nv_bfloat16* oL = (z == 0) ? g_Ql : (z == 1) ? g_Kl : g_Vl;
    float alpha = (z == 0) ? (float)ALPHA_Q : 1.0f;
    gemm_core(sb, g_xh, g_xl, Bh, Bl, oH, oL, nullptr, alpha, m0, n0);
}

// Output projection: A = attention result (hi/lo), B = Wo, out = fp32.
__global__ void __launch_bounds__(256)
gemm_out(float* __restrict__ out)
{
    extern __shared__ __align__(128) char sm_g[];
    const uint32_t sb = smem_u32(sm_g);
    gemm_core(sb, g_Ah, g_Al, g_woh, g_wol, nullptr, nullptr, out, 1.0f,
              blockIdx.y * 128, blockIdx.x * 128);
}

// ---------------------------------------------------------------------------
// Flash attention, bf16-split mma.sync, DOUBLE-BUFFERED K/V.
// 256 threads = 8 warps x 16 q rows; CTA = 128 q rows x 1 head; key tile 64.
// smem: Q hi/lo 32KB @0, two KV stages of 32KB @32768 + st*32768.
// ---------------------------------------------------------------------------
#define SQH 0
#define SQL 16384
#define SKV0 32768
#define KV_STAGE 32768
#define OKH 0
#define OKL 8192
#define OVH 16384
#define OVL 24576
#define FLASH_SMEM (32768 + 2 * KV_STAGE)   // 98304

__global__ void __launch_bounds__(256)
flash_mma(__nv_bfloat16* __restrict__ Ah_, __nv_bfloat16* __restrict__ Al_)
{
    extern __shared__ __align__(128) char sm_f[];
    const uint32_t sb = smem_u32(sm_f);
    const int tid = threadIdx.x, lane = tid & 31, w = tid >> 5;
    const int h = blockIdx.y, q0 = blockIdx.x * 128;

    auto ldKV = [&](int kt) {
        uint32_t st = sb + SKV0 + (uint32_t)(kt & 1) * KV_STAGE;
        size_t kr = (size_t)kt * 64;
#pragma unroll
        for (int i = 0; i < 2; i++) {
            int lin = tid + i * 256;            // 0..511
            int row = lin >> 3, cb = (lin & 7) << 4;
            size_t go = (kr + row) * 2048 + (size_t)h * 128 + cb;
            uint32_t so = swz(row, cb);
            cp_async16(st + OKH + so, (const char*)g_Kh + go);
            cp_async16(st + OKL + so, (const char*)g_Kl + go);
            cp_async16(st + OVH + so, (const char*)g_Vh + go);
            cp_async16(st + OVL + so, (const char*)g_Vl + go);
        }
        cp_commit();
    };

    // Q tile: 128 rows x 128B, hi + lo (own commit group)
#pragma unroll
    for (int i = 0; i < 4; i++) {
        int lin = tid + i * 256;
        int row = lin >> 3, cb = (lin & 7) << 4;
        size_t go = (size_t)(q0 + row) * 2048 + (size_t)h * 128 + cb;
        cp_async16(sb + SQH + swz(row, cb), (const char*)g_Qh + go);
        cp_async16(sb + SQL + swz(row, cb), (const char*)g_Ql + go);
    }
    cp_commit();
    ldKV(0);
    ldKV(1);

    cp_wait<2>();          // Q complete; KV0/KV1 may pend
    __syncthreads();

    // Persistent Q fragments (hi and lo)
    uint32_t qh[4][4], ql[4][4];
    {
        int row = w * 16 + (lane & 15);
#pragma unroll
        for (int kk = 0; kk < 4; kk++) {
            int cb = kk * 32 + ((lane & 16) ? 16 : 0);
            ldsm_x4(qh[kk], sb + SQH + swz(row, cb));
            ldsm_x4(ql[kk], sb + SQL + swz(row, cb));
        }
    }

    float m0v = -INFINITY, m1v = -INFINITY, l0v = 0.f, l1v = 0.f;
    float o[8][4];
#pragma unroll
    for (int d = 0; d < 8; d++)
#pragma unroll
        for (int j = 0; j < 4; j++) o[d][j] = 0.f;

    for (int kt = 0; kt < 32; kt++) {
        if (kt == 31) cp_wait<0>(); else cp_wait<1>();
        __syncthreads();
        const uint32_t st = sb + SKV0 + (uint32_t)(kt & 1) * KV_STAGE;

        // ---- S = Q K^T (3-term split), 64 keys ----
        float c[8][4];
#pragma unroll
        for (int nt = 0; nt < 8; nt++)
#pragma unroll
            for (int j = 0; j < 4; j++) c[nt][j] = 0.f;

#pragma unroll
        for (int kk = 0; kk < 4; kk++) {
#pragma unroll
            for (int ng = 0; ng < 4; ng++) {
                uint32_t bh[4], bl[4];
                int row = ng * 16 + (lane & 7) + ((lane & 16) ? 8 : 0);
                int cb = kk * 32 + ((lane & 8) ? 16 : 0);
                ldsm_x4(bh, st + OKH + swz(row, cb));
                ldsm_x4(bl, st + OKL + swz(row, cb));
                mma_bf16(c[2 * ng],     qh[kk], bh);
                mma_bf16(c[2 * ng],     ql[kk], bh);
                mma_bf16(c[2 * ng],     qh[kk], bl);
                mma_bf16(c[2 * ng + 1], qh[kk], bh + 2);
                mma_bf16(c[2 * ng + 1], ql[kk], bh + 2);
                mma_bf16(c[2 * ng + 1], qh[kk], bl + 2);
            }
        }

        // ---- online softmax (rows gid and gid+8) ----
        float mx0 = -INFINITY, mx1 = -INFINITY;
#pragma unroll
        for (int nt = 0; nt < 8; nt++) {
            mx0 = fmaxf(mx0, fmaxf(c[nt][0], c[nt][1]));
            mx1 = fmaxf(mx1, fmaxf(c[nt][2], c[nt][3]));
        }
        mx0 = fmaxf(mx0, __shfl_xor_sync(0xffffffffu, mx0, 1));
        mx0 = fmaxf(mx0, __shfl_xor_sync(0xffffffffu, mx0, 2));
        mx1 = fmaxf(mx1, __shfl_xor_sync(0xffffffffu, mx1, 1));
        mx1 = fmaxf(mx1, __shfl_xor_sync(0xffffffffu, mx1, 2));
        float mn0 = fmaxf(m0v, mx0), mn1 = fmaxf(m1v, mx1);
        float cor0 = ex2(m0v - mn0), cor1 = ex2(m1v - mn1);
        float rs0 = 0.f, rs1 = 0.f;
#pragma unroll
        for (int nt = 0; nt < 8; nt++) {
            c[nt][0] = ex2(c[nt][0] - mn0);
            c[nt][1] = ex2(c[nt][1] - mn0);
            c[nt][2] = ex2(c[nt][2] - mn1);
            c[nt][3] = ex2(c[nt][3] - mn1);
            rs0 += c[nt][0] + c[nt][1];
            rs1 += c[nt][2] + c[nt][3];
        }
        rs0 += __shfl_xor_sync(0xffffffffu, rs0, 1);
        rs0 += __shfl_xor_sync(0xffffffffu, rs0, 2);
        rs1 += __shfl_xor_sync(0xffffffffu, rs1, 1);
        rs1 += __shfl_xor_sync(0xffffffffu, rs1, 2);
        l0v = l0v * cor0 + rs0;
        l1v = l1v * cor1 + rs1;
        m0v = mn0; m1v = mn1;
#pragma unroll
        for (int d = 0; d < 8; d++) {
            o[d][0] *= cor0; o[d][1] *= cor0;
            o[d][2] *= cor1; o[d][3] *= cor1;
        }

        // ---- O += P V (3-term split), V via ldmatrix.trans ----
#pragma unroll
        for (int kk = 0; kk < 4; kk++) {
            uint32_t ah[4], al[4];
            split2(c[2 * kk][0],     c[2 * kk][1],     ah[0], al[0]);
            split2(c[2 * kk][2],     c[2 * kk][3],     ah[1], al[1]);
            split2(c[2 * kk + 1][0], c[2 * kk + 1][1], ah[2], al[2]);
            split2(c[2 * kk + 1][2], c[2 * kk + 1][3], ah[3], al[3]);
            int row = kk * 16 + (lane & 15);
#pragma unroll
            for (int dg = 0; dg < 4; dg++) {
                uint32_t bh[4], bl[4];
                int cb = dg * 32 + ((lane & 16) ? 16 : 0);
                ldsm_x4_t(bh, st + OVH + swz(row, cb));
                ldsm_x4_t(bl, st + OVL + swz(row, cb));
                mma_bf16(o[2 * dg],     ah, bh);
                mma_bf16(o[2 * dg],     al, bh);
                mma_bf16(o[2 * dg],     ah, bl);
                mma_bf16(o[2 * dg + 1], ah, bh + 2);
                mma_bf16(o[2 * dg + 1], al, bh + 2);
                mma_bf16(o[2 * dg + 1], ah, bl + 2);
            }
        }
        __syncthreads();                    // all warps done reading this stage
        if (kt + 2 < 32) ldKV(kt + 2);      // prefetch into freed stage
    }

    // ---- epilogue ----
    float inv0 = 1.f / l0v, inv1 = 1.f / l1v;
    const int gid = lane >> 2, t2 = (lane & 3) * 2;
    int r0 = q0 + w * 16 + gid;
#pragma unroll
    for (int d = 0; d < 8; d++) {
        int col = h * 64 + d * 8 + t2;
        uint32_t hb, lb;
        size_t i0 = ((size_t)r0 * 1024 + col) >> 1;
        split2(o[d][0] * inv0, o[d][1] * inv0, hb, lb);
        ((uint32_t*)Ah_)[i0] = hb;
        ((uint32_t*)Al_)[i0] = lb;
        size_t i1 = ((size_t)(r0 + 8) * 1024 + col) >> 1;
        split2(o[d][2] * inv1, o[d][3] * inv1, hb, lb);
        ((uint32_t*)Ah_)[i1] = hb;
        ((uint32_t*)Al_)[i1] = lb;
    }
}

// ---------------------------------------------------------------------------
// Launch
// ---------------------------------------------------------------------------
extern "C" void kernel_launch(void* const* d_in, const int* in_sizes, int n_in,
                              void* d_out, int out_size)
{
    (void)in_sizes; (void)n_in; (void)out_size;
    const float* x  = (const float*)d_in[0];
    const float* Wq = (const float*)d_in[1];
    const float* Wk = (const float*)d_in[2];
    const float* Wv = (const float*)d_in[3];
    const float* Wo = (const float*)d_in[4];
    float* out = (float*)d_out;

    __nv_bfloat16 *Ah, *Al;
    cudaGetSymbolAddress((void**)&Ah, g_Ah);
    cudaGetSymbolAddress((void**)&Al, g_Al);

    cudaFuncSetAttribute(gemm_qkv, cudaFuncAttributeMaxDynamicSharedMemorySize, GEMM_SMEM);
    cudaFuncSetAttribute(gemm_out, cudaFuncAttributeMaxDynamicSharedMemorySize, GEMM_SMEM);
    cudaFuncSetAttribute(flash_mma, cudaFuncAttributeMaxDynamicSharedMemorySize, FLASH_SMEM);

    split_all<<<(N4_TOTAL + 255) / 256, 256>>>(x, Wq, Wk, Wv, Wo);

    gemm_qkv<<<dim3(HD / 128, S_LEN / 128, 3), 256, GEMM_SMEM>>>();

    flash_mma<<<dim3(S_LEN / 128, 16), 256, FLASH_SMEM>>>(Ah, Al);

    gemm_out<<<dim3(HD / 128, S_LEN / 128), 256, GEMM_SMEM>>>(out);
}

// round 9
// speedup vs baseline: 4.5704x; 1.4629x over previous
#include <cuda_runtime.h>
#include <cuda_fp16.h>
#include <math.h>
#include <cstdint>

#define S_LEN 2048
#define HD    1024
#define ALPHA_Q 0.1803368801111601f   // 0.125 * log2(e)

// ---------------------------------------------------------------------------
// Scratch (device globals) — fp16 scheme:
//   x: hi+lo (exact-ish A side).  Weights: fp16 only (2-term products).
//   Q: hi+lo (Q-side split in QK^T).  K, V: fp16 only.  A: hi+lo.
// ---------------------------------------------------------------------------
__device__ __align__(16) __half g_xh[S_LEN * HD], g_xl[S_LEN * HD];
__device__ __align__(16) __half g_wq[HD * HD], g_wk[HD * HD];
__device__ __align__(16) __half g_wv[HD * HD], g_wo[HD * HD];
__device__ __align__(16) __half g_Qh[S_LEN * HD], g_Ql[S_LEN * HD];
__device__ __align__(16) __half g_K[S_LEN * HD],  g_V[S_LEN * HD];
__device__ __align__(16) __half g_Ah[S_LEN * HD], g_Al[S_LEN * HD];

// ---------------------------------------------------------------------------
// Portable PTX helpers (sm_80-level, legal on bare sm_103)
// ---------------------------------------------------------------------------
__device__ __forceinline__ uint32_t smem_u32(const void* p) {
    uint32_t a;
    asm("{ .reg .u64 t; cvta.to.shared.u64 t, %1; cvt.u32.u64 %0, t; }"
        : "=r"(a) : "l"(p));
    return a;
}
__device__ __forceinline__ void cp_async16(uint32_t dst, const void* src) {
    asm volatile("cp.async.cg.shared.global [%0], [%1], 16;" :: "r"(dst), "l"(src));
}
__device__ __forceinline__ void cp_commit() {
    asm volatile("cp.async.commit_group;" ::: "memory");
}
template<int N> __device__ __forceinline__ void cp_wait() {
    asm volatile("cp.async.wait_group %0;" :: "n"(N) : "memory");
}
__device__ __forceinline__ void ldsm_x4(uint32_t* r, uint32_t a) {
    asm volatile("ldmatrix.sync.aligned.m8n8.x4.shared.b16 {%0,%1,%2,%3}, [%4];"
                 : "=r"(r[0]), "=r"(r[1]), "=r"(r[2]), "=r"(r[3]) : "r"(a));
}
__device__ __forceinline__ void ldsm_x4_t(uint32_t* r, uint32_t a) {
    asm volatile("ldmatrix.sync.aligned.m8n8.x4.trans.shared.b16 {%0,%1,%2,%3}, [%4];"
                 : "=r"(r[0]), "=r"(r[1]), "=r"(r[2]), "=r"(r[3]) : "r"(a));
}
__device__ __forceinline__ void mma_f16(float* c, const uint32_t* a, const uint32_t* b) {
    asm volatile(
        "mma.sync.aligned.m16n8k16.row.col.f32.f16.f16.f32 "
        "{%0,%1,%2,%3}, {%4,%5,%6,%7}, {%8,%9}, {%0,%1,%2,%3};"
        : "+f"(c[0]), "+f"(c[1]), "+f"(c[2]), "+f"(c[3])
        : "r"(a[0]), "r"(a[1]), "r"(a[2]), "r"(a[3]), "r"(b[0]), "r"(b[1]));
}
__device__ __forceinline__ float ex2(float x) {
    float r; asm("ex2.approx.f32 %0, %1;" : "=f"(r) : "f"(x)); return r;
}
// 128B-row swizzle; cb must be 16B aligned
__device__ __forceinline__ uint32_t swz(int row, int cb) {
    return (uint32_t)(row * 128 + (cb ^ ((row & 7) << 4)));
}
// pack two floats to f16x2 (x -> low half)
__device__ __forceinline__ uint32_t pack2h(float x, float y) {
    uint32_t r;
    asm("cvt.rn.f16x2.f32 %0, %1, %2;" : "=r"(r) : "f"(y), "f"(x));
    return r;
}
// two floats -> f16x2 hi + f16x2 lo (round-to-nearest split)
__device__ __forceinline__ void split2h(float x, float y, uint32_t& hi, uint32_t& lo) {
    hi = pack2h(x, y);
    __half2 h = *reinterpret_cast<__half2*>(&hi);
    float rx = x - __half2float(h.x);
    float ry = y - __half2float(h.y);
    lo = pack2h(rx, ry);
}

// ---------------------------------------------------------------------------
// Fused conversion: x -> fp16 hi/lo ; Wq/Wk/Wv/Wo -> fp16 (single) — ONE launch.
// ---------------------------------------------------------------------------
#define N4_X 524288
#define N4_W 262144
#define N4_TOTAL (N4_X + 4 * N4_W)

__global__ void __launch_bounds__(256)
split_all(const float* __restrict__ x,  const float* __restrict__ Wq,
          const float* __restrict__ Wk, const float* __restrict__ Wv,
          const float* __restrict__ Wo)
{
    int i = blockIdx.x * blockDim.x + threadIdx.x;
    if (i >= N4_TOTAL) return;
    int j = i;
    if (j < N4_X) {
        float4 v = ((const float4*)x)[j];
        uint32_t h0, l0, h1, l1;
        split2h(v.x, v.y, h0, l0);
        split2h(v.z, v.w, h1, l1);
        ((uint32_t*)g_xh)[2 * j + 0] = h0;
        ((uint32_t*)g_xh)[2 * j + 1] = h1;
        ((uint32_t*)g_xl)[2 * j + 0] = l0;
        ((uint32_t*)g_xl)[2 * j + 1] = l1;
        return;
    }
    j -= N4_X;
    const float* in;
    __half* w;
    if (j < N4_W)      { in = Wq; w = g_wq; }
    else if ((j -= N4_W) < N4_W) { in = Wk; w = g_wk; }
    else if ((j -= N4_W) < N4_W) { in = Wv; w = g_wv; }
    else               { j -= N4_W; in = Wo; w = g_wo; }
    float4 v = ((const float4*)in)[j];
    ((uint32_t*)w)[2 * j + 0] = pack2h(v.x, v.y);
    ((uint32_t*)w)[2 * j + 1] = pack2h(v.z, v.w);
}

// ---------------------------------------------------------------------------
// Split-GEMM core: C[2048,1024] = (Ah + Al) * B^T, 2 sections, fp16 mma.
// Block 128x128, BK=64, 8 warps, double-buffered cp.async.
// Output modes: outF (fp32) | outHi+outLo (fp16 split) | outHi only (fp16).
// ---------------------------------------------------------------------------
#define G_STAGE 32768
#define GEMM_SMEM (2 * G_STAGE)
#define NCHUNK 32

__device__ __forceinline__ void gemm_core(
    uint32_t sb,
    const __half* Ah, const __half* Al, const __half* B,
    __half* outHi, __half* outLo, float* outF,
    float alpha, int m0, int n0)
{
    const int tid = threadIdx.x;
    const int lane = tid & 31, wid = tid >> 5;
    const int wm = wid & 3, wn = wid >> 2;

    const __half* Asec[2] = {Ah, Al};

    float c[2][8][4];
#pragma unroll
    for (int mt = 0; mt < 2; mt++)
#pragma unroll
        for (int nt = 0; nt < 8; nt++)
#pragma unroll
            for (int j = 0; j < 4; j++) c[mt][nt][j] = 0.f;

    auto issue = [&](int ck, int stage) {
        int sec = ck >> 4;
        size_t ko = (size_t)(ck & 15) * 128;
        const char* Ab = (const char*)Asec[sec];
        const char* Bb = (const char*)B;
        uint32_t dA = sb + stage * G_STAGE;
        uint32_t dB = dA + 16384;
#pragma unroll
        for (int i = 0; i < 4; i++) {
            int lin = tid + i * 256;
            int row = lin >> 3, cb = (lin & 7) << 4;
            cp_async16(dA + swz(row, cb), Ab + (size_t)(m0 + row) * 2048 + ko + cb);
            cp_async16(dB + swz(row, cb), Bb + (size_t)(n0 + row) * 2048 + ko + cb);
        }
        cp_commit();
    };

    issue(0, 0);
    issue(1, 1);

    for (int ck = 0; ck < NCHUNK; ck++) {
        if (ck == NCHUNK - 1) cp_wait<0>(); else cp_wait<1>();
        __syncthreads();
        uint32_t aB = sb + (ck & 1) * G_STAGE;
        uint32_t bB = aB + 16384;
#pragma unroll
        for (int kk = 0; kk < 4; kk++) {
            uint32_t afr[2][4], bfr[8][2];
#pragma unroll
            for (int mt = 0; mt < 2; mt++) {
                int row = wm * 32 + mt * 16 + (lane & 15);
                int cb = kk * 32 + ((lane & 16) ? 16 : 0);
                ldsm_x4(afr[mt], aB + swz(row, cb));
            }
#pragma unroll
            for (int ng = 0; ng < 4; ng++) {
                uint32_t t[4];
                int row = wn * 64 + ng * 16 + (lane & 7) + ((lane & 16) ? 8 : 0);
                int cb = kk * 32 + ((lane & 8) ? 16 : 0);
                ldsm_x4(t, bB + swz(row, cb));
                bfr[2 * ng][0] = t[0];     bfr[2 * ng][1] = t[1];
                bfr[2 * ng + 1][0] = t[2]; bfr[2 * ng + 1][1] = t[3];
            }
#pragma unroll
            for (int mt = 0; mt < 2; mt++)
#pragma unroll
                for (int nt = 0; nt < 8; nt++)
                    mma_f16(c[mt][nt], afr[mt], bfr[nt]);
        }
        __syncthreads();
        if (ck + 2 < NCHUNK) issue(ck + 2, ck & 1);
    }

    const int gid = lane >> 2, t2 = (lane & 3) * 2;
#pragma unroll
    for (int mt = 0; mt < 2; mt++)
#pragma unroll
        for (int hh = 0; hh < 2; hh++) {
            int row = m0 + wm * 32 + mt * 16 + gid + hh * 8;
#pragma unroll
            for (int nt = 0; nt < 8; nt++) {
                int col = n0 + wn * 64 + nt * 8 + t2;
                float v0 = c[mt][nt][2 * hh] * alpha;
                float v1 = c[mt][nt][2 * hh + 1] * alpha;
                size_t idx = (size_t)row * 1024 + col;
                if (outF) {
                    *(float2*)(outF + idx) = make_float2(v0, v1);
                } else if (outLo) {
                    uint32_t hb, lb;
                    split2h(v0, v1, hb, lb);
                    ((uint32_t*)outHi)[idx >> 1] = hb;
                    ((uint32_t*)outLo)[idx >> 1] = lb;
                } else {
                    ((uint32_t*)outHi)[idx >> 1] = pack2h(v0, v1);
                }
            }
        }
}

// Fused Q/K/V projections: blockIdx.z selects weight + destination.
__global__ void __launch_bounds__(256)
gemm_qkv()
{
    extern __shared__ __align__(128) char sm_g[];
    const uint32_t sb = smem_u32(sm_g);
    const int m0 = blockIdx.y * 128, n0 = blockIdx.x * 128;
    const int z = blockIdx.z;
    if (z == 0)
        gemm_core(sb, g_xh, g_xl, g_wq, g_Qh, g_Ql, nullptr, (float)ALPHA_Q, m0, n0);
    else if (z == 1)
        gemm_core(sb, g_xh, g_xl, g_wk, g_K, nullptr, nullptr, 1.0f, m0, n0);
    else
        gemm_core(sb, g_xh, g_xl, g_wv, g_V, nullptr, nullptr, 1.0f, m0, n0);
}

// Output projection: A (hi/lo) x Wo -> fp32 out.
__global__ void __launch_bounds__(256)
gemm_out(float* __restrict__ out)
{
    extern __shared__ __align__(128) char sm_g[];
    const uint32_t sb = smem_u32(sm_g);
    gemm_core(sb, g_Ah, g_Al, g_wo, nullptr, nullptr, out, 1.0f,
              blockIdx.y * 128, blockIdx.x * 128);
}

// ---------------------------------------------------------------------------
// Flash attention, fp16 mma, double-buffered K/V (fp16-only K and V).
// 256 threads = 8 warps x 16 q rows; CTA = 128 q rows x 1 head; key tile 64.
// S = (Qh + Ql) * K^T ; P = exp2(S - m), split hi/lo ; O += (Ph + Pl) * V.
// smem: Qh 16K @0, Ql 16K @16384; stages @32768: {K 8K, V 8K} x2 = 64KB total.
// ---------------------------------------------------------------------------
#define SQH 0
#define SQL 16384
#define SKV0 32768
#define KV_STAGE 16384
#define OK 0
#define OV 8192
#define FLASH_SMEM (32768 + 2 * KV_STAGE)   // 65536

__global__ void __launch_bounds__(256)
flash_mma(__half* __restrict__ Ah_, __half* __restrict__ Al_)
{
    extern __shared__ __align__(128) char sm_f[];
    const uint32_t sb = smem_u32(sm_f);
    const int tid = threadIdx.x, lane = tid & 31, w = tid >> 5;
    const int h = blockIdx.y, q0 = blockIdx.x * 128;

    auto ldKV = [&](int kt) {
        uint32_t st = sb + SKV0 + (uint32_t)(kt & 1) * KV_STAGE;
        size_t kr = (size_t)kt * 64;
#pragma unroll
        for (int i = 0; i < 2; i++) {
            int lin = tid + i * 256;            // 0..511
            int row = lin >> 3, cb = (lin & 7) << 4;
            size_t go = (kr + row) * 2048 + (size_t)h * 128 + cb;
            uint32_t so = swz(row, cb);
            cp_async16(st + OK + so, (const char*)g_K + go);
            cp_async16(st + OV + so, (const char*)g_V + go);
        }
        cp_commit();
    };

    // Q tile: 128 rows x 128B, hi + lo (own commit group)
#pragma unroll
    for (int i = 0; i < 4; i++) {
        int lin = tid + i * 256;
        int row = lin >> 3, cb = (lin & 7) << 4;
        size_t go = (size_t)(q0 + row) * 2048 + (size_t)h * 128 + cb;
        cp_async16(sb + SQH + swz(row, cb), (const char*)g_Qh + go);
        cp_async16(sb + SQL + swz(row, cb), (const char*)g_Ql + go);
    }
    cp_commit();
    ldKV(0);
    ldKV(1);

    cp_wait<2>();          // Q complete; KV0/KV1 may pend
    __syncthreads();

    // Persistent Q fragments (hi and lo)
    uint32_t qh[4][4], ql[4][4];
    {
        int row = w * 16 + (lane & 15);
#pragma unroll
        for (int kk = 0; kk < 4; kk++) {
            int cb = kk * 32 + ((lane & 16) ? 16 : 0);
            ldsm_x4(qh[kk], sb + SQH + swz(row, cb));
            ldsm_x4(ql[kk], sb + SQL + swz(row, cb));
        }
    }

    float m0v = -INFINITY, m1v = -INFINITY, l0v = 0.f, l1v = 0.f;
    float o[8][4];
#pragma unroll
    for (int d = 0; d < 8; d++)
#pragma unroll
        for (int j = 0; j < 4; j++) o[d][j] = 0.f;

    for (int kt = 0; kt < 32; kt++) {
        if (kt == 31) cp_wait<0>(); else cp_wait<1>();
        __syncthreads();
        const uint32_t st = sb + SKV0 + (uint32_t)(kt & 1) * KV_STAGE;

        // ---- S = (Qh + Ql) K^T, 64 keys ----
        float c[8][4];
#pragma unroll
        for (int nt = 0; nt < 8; nt++)
#pragma unroll
            for (int j = 0; j < 4; j++) c[nt][j] = 0.f;

#pragma unroll
        for (int kk = 0; kk < 4; kk++) {
#pragma unroll
            for (int ng = 0; ng < 4; ng++) {
                uint32_t bh[4];
                int row = ng * 16 + (lane & 7) + ((lane & 16) ? 8 : 0);
                int cb = kk * 32 + ((lane & 8) ? 16 : 0);
                ldsm_x4(bh, st + OK + swz(row, cb));
                mma_f16(c[2 * ng],     qh[kk], bh);
                mma_f16(c[2 * ng],     ql[kk], bh);
                mma_f16(c[2 * ng + 1], qh[kk], bh + 2);
                mma_f16(c[2 * ng + 1], ql[kk], bh + 2);
            }
        }

        // ---- online softmax (rows gid and gid+8) ----
        float mx0 = -INFINITY, mx1 = -INFINITY;
#pragma unroll
        for (int nt = 0; nt < 8; nt++) {
            mx0 = fmaxf(mx0, fmaxf(c[nt][0], c[nt][1]));
            mx1 = fmaxf(mx1, fmaxf(c[nt][2], c[nt][3]));
        }
        mx0 = fmaxf(mx0, __shfl_xor_sync(0xffffffffu, mx0, 1));
        mx0 = fmaxf(mx0, __shfl_xor_sync(0xffffffffu, mx0, 2));
        mx1 = fmaxf(mx1, __shfl_xor_sync(0xffffffffu, mx1, 1));
        mx1 = fmaxf(mx1, __shfl_xor_sync(0xffffffffu, mx1, 2));
        float mn0 = fmaxf(m0v, mx0), mn1 = fmaxf(m1v, mx1);
        float cor0 = ex2(m0v - mn0), cor1 = ex2(m1v - mn1);
        float rs0 = 0.f, rs1 = 0.f;
#pragma unroll
        for (int nt = 0; nt < 8; nt++) {
            c[nt][0] = ex2(c[nt][0] - mn0);
            c[nt][1] = ex2(c[nt][1] - mn0);
            c[nt][2] = ex2(c[nt][2] - mn1);
            c[nt][3] = ex2(c[nt][3] - mn1);
            rs0 += c[nt][0] + c[nt][1];
            rs1 += c[nt][2] + c[nt][3];
        }
        rs0 += __shfl_xor_sync(0xffffffffu, rs0, 1);
        rs0 += __shfl_xor_sync(0xffffffffu, rs0, 2);
        rs1 += __shfl_xor_sync(0xffffffffu, rs1, 1);
        rs1 += __shfl_xor_sync(0xffffffffu, rs1, 2);
        l0v = l0v * cor0 + rs0;
        l1v = l1v * cor1 + rs1;
        m0v = mn0; m1v = mn1;
#pragma unroll
        for (int d = 0; d < 8; d++) {
            o[d][0] *= cor0; o[d][1] *= cor0;
            o[d][2] *= cor1; o[d][3] *= cor1;
        }

        // ---- O += (Ph + Pl) V, V via ldmatrix.trans ----
#pragma unroll
        for (int kk = 0; kk < 4; kk++) {
            uint32_t ah[4], al[4];
            split2h(c[2 * kk][0],     c[2 * kk][1],     ah[0], al[0]);
            split2h(c[2 * kk][2],     c[2 * kk][3],     ah[1], al[1]);
            split2h(c[2 * kk + 1][0], c[2 * kk + 1][1], ah[2], al[2]);
            split2h(c[2 * kk + 1][2], c[2 * kk + 1][3], ah[3], al[3]);
            int row = kk * 16 + (lane & 15);
#pragma unroll
            for (int dg = 0; dg < 4; dg++) {
                uint32_t bh[4];
                int cb = dg * 32 + ((lane & 16) ? 16 : 0);
                ldsm_x4_t(bh, st + OV + swz(row, cb));
                mma_f16(o[2 * dg],     ah, bh);
                mma_f16(o[2 * dg],     al, bh);
                mma_f16(o[2 * dg + 1], ah, bh + 2);
                mma_f16(o[2 * dg + 1], al, bh + 2);
            }
        }
        __syncthreads();                    // all warps done reading this stage
        if (kt + 2 < 32) ldKV(kt + 2);      // prefetch into freed stage
    }

    // ---- epilogue ----
    float inv0 = 1.f / l0v, inv1 = 1.f / l1v;
    const int gid = lane >> 2, t2 = (lane & 3) * 2;
    int r0 = q0 + w * 16 + gid;
#pragma unroll
    for (int d = 0; d < 8; d++) {
        int col = h * 64 + d * 8 + t2;
        uint32_t hb, lb;
        size_t i0 = ((size_t)r0 * 1024 + col) >> 1;
        split2h(o[d][0] * inv0, o[d][1] * inv0, hb, lb);
        ((uint32_t*)Ah_)[i0] = hb;
        ((uint32_t*)Al_)[i0] = lb;
        size_t i1 = ((size_t)(r0 + 8) * 1024 + col) >> 1;
        split2h(o[d][2] * inv1, o[d][3] * inv1, hb, lb);
        ((uint32_t*)Ah_)[i1] = hb;
        ((uint32_t*)Al_)[i1] = lb;
    }
}

// ---------------------------------------------------------------------------
// Launch
// ---------------------------------------------------------------------------
extern "C" void kernel_launch(void* const* d_in, const int* in_sizes, int n_in,
                              void* d_out, int out_size)
{
    (void)in_sizes; (void)n_in; (void)out_size;
    const float* x  = (const float*)d_in[0];
    const float* Wq = (const float*)d_in[1];
    const float* Wk = (const float*)d_in[2];
    const float* Wv = (const float*)d_in[3];
    const float* Wo = (const float*)d_in[4];
    float* out = (float*)d_out;

    __half *Ah, *Al;
    cudaGetSymbolAddress((void**)&Ah, g_Ah);
    cudaGetSymbolAddress((void**)&Al, g_Al);

    cudaFuncSetAttribute(gemm_qkv, cudaFuncAttributeMaxDynamicSharedMemorySize, GEMM_SMEM);
    cudaFuncSetAttribute(gemm_out, cudaFuncAttributeMaxDynamicSharedMemorySize, GEMM_SMEM);
    cudaFuncSetAttribute(flash_mma, cudaFuncAttributeMaxDynamicSharedMemorySize, FLASH_SMEM);

    split_all<<<(N4_TOTAL + 255) / 256, 256>>>(x, Wq, Wk, Wv, Wo);

    gemm_qkv<<<dim3(HD / 128, S_LEN / 128, 3), 256, GEMM_SMEM>>>();

    flash_mma<<<dim3(S_LEN / 128, 16), 256, FLASH_SMEM>>>(Ah, Al);

    gemm_out<<<dim3(HD / 128, S_LEN / 128), 256, GEMM_SMEM>>>(out);
}

// round 11
// speedup vs baseline: 4.8222x; 1.0551x over previous
#include <cuda_runtime.h>
#include <cuda_fp16.h>
#include <math.h>
#include <cstdint>

#define S_LEN 2048
#define HD    1024
#define ALPHA_Q 0.1803368801111601f   // 0.125 * log2(e)

// ---------------------------------------------------------------------------
// Scratch (device globals) — fp16 scheme:
//   x: hi+lo.  Weights: fp16 only.  Q: hi+lo.  K, V: fp16.  A: hi+lo.
// ---------------------------------------------------------------------------
__device__ __align__(16) __half g_xh[S_LEN * HD], g_xl[S_LEN * HD];
__device__ __align__(16) __half g_wq[HD * HD], g_wk[HD * HD];
__device__ __align__(16) __half g_wv[HD * HD], g_wo[HD * HD];
__device__ __align__(16) __half g_Qh[S_LEN * HD], g_Ql[S_LEN * HD];
__device__ __align__(16) __half g_K[S_LEN * HD],  g_V[S_LEN * HD];
__device__ __align__(16) __half g_Ah[S_LEN * HD], g_Al[S_LEN * HD];

// ---------------------------------------------------------------------------
// Portable PTX helpers (sm_80-level, legal on bare sm_103)
// ---------------------------------------------------------------------------
__device__ __forceinline__ uint32_t smem_u32(const void* p) {
    uint32_t a;
    asm("{ .reg .u64 t; cvta.to.shared.u64 t, %1; cvt.u32.u64 %0, t; }"
        : "=r"(a) : "l"(p));
    return a;
}
__device__ __forceinline__ void cp_async16(uint32_t dst, const void* src) {
    asm volatile("cp.async.cg.shared.global [%0], [%1], 16;" :: "r"(dst), "l"(src));
}
__device__ __forceinline__ void cp_commit() {
    asm volatile("cp.async.commit_group;" ::: "memory");
}
template<int N> __device__ __forceinline__ void cp_wait() {
    asm volatile("cp.async.wait_group %0;" :: "n"(N) : "memory");
}
__device__ __forceinline__ void ldsm_x4(uint32_t* r, uint32_t a) {
    asm volatile("ldmatrix.sync.aligned.m8n8.x4.shared.b16 {%0,%1,%2,%3}, [%4];"
                 : "=r"(r[0]), "=r"(r[1]), "=r"(r[2]), "=r"(r[3]) : "r"(a));
}
__device__ __forceinline__ void ldsm_x4_t(uint32_t* r, uint32_t a) {
    asm volatile("ldmatrix.sync.aligned.m8n8.x4.trans.shared.b16 {%0,%1,%2,%3}, [%4];"
                 : "=r"(r[0]), "=r"(r[1]), "=r"(r[2]), "=r"(r[3]) : "r"(a));
}
__device__ __forceinline__ void mma_f16(float* c, const uint32_t* a, const uint32_t* b) {
    asm volatile(
        "mma.sync.aligned.m16n8k16.row.col.f32.f16.f16.f32 "
        "{%0,%1,%2,%3}, {%4,%5,%6,%7}, {%8,%9}, {%0,%1,%2,%3};"
        : "+f"(c[0]), "+f"(c[1]), "+f"(c[2]), "+f"(c[3])
        : "r"(a[0]), "r"(a[1]), "r"(a[2]), "r"(a[3]), "r"(b[0]), "r"(b[1]));
}
__device__ __forceinline__ float ex2(float x) {
    float r; asm("ex2.approx.f32 %0, %1;" : "=f"(r) : "f"(x)); return r;
}
// 128B-row swizzle; cb must be 16B aligned
__device__ __forceinline__ uint32_t swz(int row, int cb) {
    return (uint32_t)(row * 128 + (cb ^ ((row & 7) << 4)));
}
// pack two floats to f16x2 (x -> low half)
__device__ __forceinline__ uint32_t pack2h(float x, float y) {
    uint32_t r;
    asm("cvt.rn.f16x2.f32 %0, %1, %2;" : "=r"(r) : "f"(y), "f"(x));
    return r;
}
// two floats -> f16x2 hi + f16x2 lo (round-to-nearest split)
__device__ __forceinline__ void split2h(float x, float y, uint32_t& hi, uint32_t& lo) {
    hi = pack2h(x, y);
    __half2 h = *reinterpret_cast<__half2*>(&hi);
    float rx = x - __half2float(h.x);
    float ry = y - __half2float(h.y);
    lo = pack2h(rx, ry);
}

// ---------------------------------------------------------------------------
// Fused conversion: x -> fp16 hi/lo ; Wq/Wk/Wv/Wo -> fp16 — ONE launch.
// ---------------------------------------------------------------------------
#define N4_X 524288
#define N4_W 262144
#define N4_TOTAL (N4_X + 4 * N4_W)

__global__ void __launch_bounds__(256)
split_all(const float* __restrict__ x,  const float* __restrict__ Wq,
          const float* __restrict__ Wk, const float* __restrict__ Wv,
          const float* __restrict__ Wo)
{
    int i = blockIdx.x * blockDim.x + threadIdx.x;
    if (i >= N4_TOTAL) return;
    int j = i;
    if (j < N4_X) {
        float4 v = ((const float4*)x)[j];
        uint32_t h0, l0, h1, l1;
        split2h(v.x, v.y, h0, l0);
        split2h(v.z, v.w, h1, l1);
        ((uint32_t*)g_xh)[2 * j + 0] = h0;
        ((uint32_t*)g_xh)[2 * j + 1] = h1;
        ((uint32_t*)g_xl)[2 * j + 0] = l0;
        ((uint32_t*)g_xl)[2 * j + 1] = l1;
        return;
    }
    j -= N4_X;
    const float* in;
    __half* w;
    if (j < N4_W)      { in = Wq; w = g_wq; }
    else if ((j -= N4_W) < N4_W) { in = Wk; w = g_wk; }
    else if ((j -= N4_W) < N4_W) { in = Wv; w = g_wv; }
    else               { j -= N4_W; in = Wo; w = g_wo; }
    float4 v = ((const float4*)in)[j];
    ((uint32_t*)w)[2 * j + 0] = pack2h(v.x, v.y);
    ((uint32_t*)w)[2 * j + 1] = pack2h(v.z, v.w);
}

// ---------------------------------------------------------------------------
// Split-GEMM core: C = (Ah + Al) * B^T, MERGED sections per chunk:
// each stage holds {Ah, Al, B} (48KB); B fragments loaded once per kk and
// reused in registers for both A sections (-33% LDSM, -50% B cp.async).
// Block 128x128, BK=64, 8 warps, double-buffered.
// ---------------------------------------------------------------------------
#define G_STAGE 49152
#define GEMM_SMEM (2 * G_STAGE)    // 98304
#define NCHUNK 16

__device__ __forceinline__ void gemm_core(
    uint32_t sb,
    const __half* Ah, const __half* Al, const __half* B,
    __half* outHi, __half* outLo, float* outF,
    float alpha, int m0, int n0)
{
    const int tid = threadIdx.x;
    const int lane = tid & 31, wid = tid >> 5;
    const int wm = wid & 3, wn = wid >> 2;

    float c[2][8][4];
#pragma unroll
    for (int mt = 0; mt < 2; mt++)
#pragma unroll
        for (int nt = 0; nt < 8; nt++)
#pragma unroll
            for (int j = 0; j < 4; j++) c[mt][nt][j] = 0.f;

    auto issue = [&](int ck, int stage) {
        size_t ko = (size_t)ck * 128;            // bytes into each 2048B row
        uint32_t dAh = sb + stage * G_STAGE;
        uint32_t dAl = dAh + 16384;
        uint32_t dB  = dAh + 32768;
#pragma unroll
        for (int i = 0; i < 4; i++) {
            int lin = tid + i * 256;
            int row = lin >> 3, cb = (lin & 7) << 4;
            size_t goA = (size_t)(m0 + row) * 2048 + ko + cb;
            cp_async16(dAh + swz(row, cb), (const char*)Ah + goA);
            cp_async16(dAl + swz(row, cb), (const char*)Al + goA);
            cp_async16(dB + swz(row, cb),
                       (const char*)B + (size_t)(n0 + row) * 2048 + ko + cb);
        }
        cp_commit();
    };

    issue(0, 0);
    issue(1, 1);

    for (int ck = 0; ck < NCHUNK; ck++) {
        if (ck == NCHUNK - 1) cp_wait<0>(); else cp_wait<1>();
        __syncthreads();
        uint32_t aH = sb + (ck & 1) * G_STAGE;
        uint32_t aL = aH + 16384;
        uint32_t bB = aH + 32768;
#pragma unroll
        for (int kk = 0; kk < 4; kk++) {
            uint32_t afh[2][4], afl[2][4], bfr[8][2];
#pragma unroll
            for (int mt = 0; mt < 2; mt++) {
                int row = wm * 32 + mt * 16 + (lane & 15);
                int cb = kk * 32 + ((lane & 16) ? 16 : 0);
                ldsm_x4(afh[mt], aH + swz(row, cb));
                ldsm_x4(afl[mt], aL + swz(row, cb));
            }
#pragma unroll
            for (int ng = 0; ng < 4; ng++) {
                uint32_t t[4];
                int row = wn * 64 + ng * 16 + (lane & 7) + ((lane & 16) ? 8 : 0);
                int cb = kk * 32 + ((lane & 8) ? 16 : 0);
                ldsm_x4(t, bB + swz(row, cb));
                bfr[2 * ng][0] = t[0];     bfr[2 * ng][1] = t[1];
                bfr[2 * ng + 1][0] = t[2]; bfr[2 * ng + 1][1] = t[3];
            }
#pragma unroll
            for (int mt = 0; mt < 2; mt++)
#pragma unroll
                for (int nt = 0; nt < 8; nt++) {
                    mma_f16(c[mt][nt], afh[mt], bfr[nt]);
                    mma_f16(c[mt][nt], afl[mt], bfr[nt]);
                }
        }
        __syncthreads();
        if (ck + 2 < NCHUNK) issue(ck + 2, ck & 1);
    }

    const int gid = lane >> 2, t2 = (lane & 3) * 2;
#pragma unroll
    for (int mt = 0; mt < 2; mt++)
#pragma unroll
        for (int hh = 0; hh < 2; hh++) {
            int row = m0 + wm * 32 + mt * 16 + gid + hh * 8;
#pragma unroll
            for (int nt = 0; nt < 8; nt++) {
                int col = n0 + wn * 64 + nt * 8 + t2;
                float v0 = c[mt][nt][2 * hh] * alpha;
                float v1 = c[mt][nt][2 * hh + 1] * alpha;
                size_t idx = (size_t)row * 1024 + col;
                if (outF) {
                    *(float2*)(outF + idx) = make_float2(v0, v1);
                } else if (outLo) {
                    uint32_t hb, lb;
                    split2h(v0, v1, hb, lb);
                    ((uint32_t*)outHi)[idx >> 1] = hb;
                    ((uint32_t*)outLo)[idx >> 1] = lb;
                } else {
                    ((uint32_t*)outHi)[idx >> 1] = pack2h(v0, v1);
                }
            }
        }
}

// Fused Q/K/V projections: blockIdx.z selects weight + destination.
__global__ void __launch_bounds__(256)
gemm_qkv()
{
    extern __shared__ __align__(128) char sm_g[];
    const uint32_t sb = smem_u32(sm_g);
    const int m0 = blockIdx.y * 128, n0 = blockIdx.x * 128;
    const int z = blockIdx.z;
    if (z == 0)
        gemm_core(sb, g_xh, g_xl, g_wq, g_Qh, g_Ql, nullptr, (float)ALPHA_Q, m0, n0);
    else if (z == 1)
        gemm_core(sb, g_xh, g_xl, g_wk, g_K, nullptr, nullptr, 1.0f, m0, n0);
    else
        gemm_core(sb, g_xh, g_xl, g_wv, g_V, nullptr, nullptr, 1.0f, m0, n0);
}

// Output projection: A (hi/lo) x Wo -> fp32 out.
__global__ void __launch_bounds__(256)
gemm_out(float* __restrict__ out)
{
    extern __shared__ __align__(128) char sm_g[];
    const uint32_t sb = smem_u32(sm_g);
    gemm_core(sb, g_Ah, g_Al, g_wo, nullptr, nullptr, out, 1.0f,
              blockIdx.y * 128, blockIdx.x * 128);
}

// ---------------------------------------------------------------------------
// Flash attention, fp16 mma, double-buffered K/V — unchanged from R9.
// ---------------------------------------------------------------------------
#define SQH 0
#define SQL 16384
#define SKV0 32768
#define KV_STAGE 16384
#define OK 0
#define OV 8192
#define FLASH_SMEM (32768 + 2 * KV_STAGE)   // 65536

__global__ void __launch_bounds__(256)
flash_mma(__half* __restrict__ Ah_, __half* __restrict__ Al_)
{
    extern __shared__ __align__(128) char sm_f[];
    const uint32_t sb = smem_u32(sm_f);
    const int tid = threadIdx.x, lane = tid & 31, w = tid >> 5;
    const int h = blockIdx.y, q0 = blockIdx.x * 128;

    auto ldKV = [&](int kt) {
        uint32_t st = sb + SKV0 + (uint32_t)(kt & 1) * KV_STAGE;
        size_t kr = (size_t)kt * 64;
#pragma unroll
        for (int i = 0; i < 2; i++) {
            int lin = tid + i * 256;
            int row = lin >> 3, cb = (lin & 7) << 4;
            size_t go = (kr + row) * 2048 + (size_t)h * 128 + cb;
            uint32_t so = swz(row, cb);
            cp_async16(st + OK + so, (const char*)g_K + go);
            cp_async16(st + OV + so, (const char*)g_V + go);
        }
        cp_commit();
    };

#pragma unroll
    for (int i = 0; i < 4; i++) {
        int lin = tid + i * 256;
        int row = lin >> 3, cb = (lin & 7) << 4;
        size_t go = (size_t)(q0 + row) * 2048 + (size_t)h * 128 + cb;
        cp_async16(sb + SQH + swz(row, cb), (const char*)g_Qh + go);
        cp_async16(sb + SQL + swz(row, cb), (const char*)g_Ql + go);
    }
    cp_commit();
    ldKV(0);
    ldKV(1);

    cp_wait<2>();
    __syncthreads();

    uint32_t qh[4][4], ql[4][4];
    {
        int row = w * 16 + (lane & 15);
#pragma unroll
        for (int kk = 0; kk < 4; kk++) {
            int cb = kk * 32 + ((lane & 16) ? 16 : 0);
            ldsm_x4(qh[kk], sb + SQH + swz(row, cb));
            ldsm_x4(ql[kk], sb + SQL + swz(row, cb));
        }
    }

    float m0v = -INFINITY, m1v = -INFINITY, l0v = 0.f, l1v = 0.f;
    float o[8][4];
#pragma unroll
    for (int d = 0; d < 8; d++)
#pragma unroll
        for (int j = 0; j < 4; j++) o[d][j] = 0.f;

    for (int kt = 0; kt < 32; kt++) {
        if (kt == 31) cp_wait<0>(); else cp_wait<1>();
        __syncthreads();
        const uint32_t st = sb + SKV0 + (uint32_t)(kt & 1) * KV_STAGE;

        float c[8][4];
#pragma unroll
        for (int nt = 0; nt < 8; nt++)
#pragma unroll
            for (int j = 0; j < 4; j++) c[nt][j] = 0.f;

#pragma unroll
        for (int kk = 0; kk < 4; kk++) {
#pragma unroll
            for (int ng = 0; ng < 4; ng++) {
                uint32_t bh[4];
                int row = ng * 16 + (lane & 7) + ((lane & 16) ? 8 : 0);
                int cb = kk * 32 + ((lane & 8) ? 16 : 0);
                ldsm_x4(bh, st + OK + swz(row, cb));
                mma_f16(c[2 * ng],     qh[kk], bh);
                mma_f16(c[2 * ng],     ql[kk], bh);
                mma_f16(c[2 * ng + 1], qh[kk], bh + 2);
                mma_f16(c[2 * ng + 1], ql[kk], bh + 2);
            }
        }

        float mx0 = -INFINITY, mx1 = -INFINITY;
#pragma unroll
        for (int nt = 0; nt < 8; nt++) {
            mx0 = fmaxf(mx0, fmaxf(c[nt][0], c[nt][1]));
            mx1 = fmaxf(mx1, fmaxf(c[nt][2], c[nt][3]));
        }
        mx0 = fmaxf(mx0, __shfl_xor_sync(0xffffffffu, mx0, 1));
        mx0 = fmaxf(mx0, __shfl_xor_sync(0xffffffffu, mx0, 2));
        mx1 = fmaxf(mx1, __shfl_xor_sync(0xffffffffu, mx1, 1));
        mx1 = fmaxf(mx1, __shfl_xor_sync(0xffffffffu, mx1, 2));
        float mn0 = fmaxf(m0v, mx0), mn1 = fmaxf(m1v, mx1);
        float cor0 = ex2(m0v - mn0), cor1 = ex2(m1v - mn1);
        float rs0 = 0.f, rs1 = 0.f;
#pragma unroll
        for (int nt = 0; nt < 8; nt++) {
            c[nt][0] = ex2(c[nt][0] - mn0);
            c[nt][1] = ex2(c[nt][1] - mn0);
            c[nt][2] = ex2(c[nt][2] - mn1);
            c[nt][3] = ex2(c[nt][3] - mn1);
            rs0 += c[nt][0] + c[nt][1];
            rs1 += c[nt][2] + c[nt][3];
        }
        rs0 += __shfl_xor_sync(0xffffffffu, rs0, 1);
        rs0 += __shfl_xor_sync(0xffffffffu, rs0, 2);
        rs1 += __shfl_xor_sync(0xffffffffu, rs1, 1);
        rs1 += __shfl_xor_sync(0xffffffffu, rs1, 2);
        l0v = l0v * cor0 + rs0;
        l1v = l1v * cor1 + rs1;
        m0v = mn0; m1v = mn1;
#pragma unroll
        for (int d = 0; d < 8; d++) {
            o[d][0] *= cor0; o[d][1] *= cor0;
            o[d][2] *= cor1; o[d][3] *= cor1;
        }

#pragma unroll
        for (int kk = 0; kk < 4; kk++) {
            uint32_t ah[4], al[4];
            split2h(c[2 * kk][0],     c[2 * kk][1],     ah[0], al[0]);
            split2h(c[2 * kk][2],     c[2 * kk][3],     ah[1], al[1]);
            split2h(c[2 * kk + 1][0], c[2 * kk + 1][1], ah[2], al[2]);
            split2h(c[2 * kk + 1][2], c[2 * kk + 1][3], ah[3], al[3]);
            int row = kk * 16 + (lane & 15);
#pragma unroll
            for (int dg = 0; dg < 4; dg++) {
                uint32_t bh[4];
                int cb = dg * 32 + ((lane & 16) ? 16 : 0);
                ldsm_x4_t(bh, st + OV + swz(row, cb));
                mma_f16(o[2 * dg],     ah, bh);
                mma_f16(o[2 * dg],     al, bh);
                mma_f16(o[2 * dg + 1], ah, bh + 2);
                mma_f16(o[2 * dg + 1], al, bh + 2);
            }
        }
        __syncthreads();
        if (kt + 2 < 32) ldKV(kt + 2);
    }

    float inv0 = 1.f / l0v, inv1 = 1.f / l1v;
    const int gid = lane >> 2, t2 = (lane & 3) * 2;
    int r0 = q0 + w * 16 + gid;
#pragma unroll
    for (int d = 0; d < 8; d++) {
        int col = h * 64 + d * 8 + t2;
        uint32_t hb, lb;
        size_t i0 = ((size_t)r0 * 1024 + col) >> 1;
        split2h(o[d][0] * inv0, o[d][1] * inv0, hb, lb);
        ((uint32_t*)Ah_)[i0] = hb;
        ((uint32_t*)Al_)[i0] = lb;
        size_t i1 = ((size_t)(r0 + 8) * 1024 + col) >> 1;
        split2h(o[d][2] * inv1, o[d][3] * inv1, hb, lb);
        ((uint32_t*)Ah_)[i1] = hb;
        ((uint32_t*)Al_)[i1] = lb;
    }
}

// ---------------------------------------------------------------------------
// Launch
// ---------------------------------------------------------------------------
extern "C" void kernel_launch(void* const* d_in, const int* in_sizes, int n_in,
                              void* d_out, int out_size)
{
    (void)in_sizes; (void)n_in; (void)out_size;
    const float* x  = (const float*)d_in[0];
    const float* Wq = (const float*)d_in[1];
    const float* Wk = (const float*)d_in[2];
    const float* Wv = (const float*)d_in[3];
    const float* Wo = (const float*)d_in[4];
    float* out = (float*)d_out;

    __half *Ah, *Al;
    cudaGetSymbolAddress((void**)&Ah, g_Ah);
    cudaGetSymbolAddress((void**)&Al, g_Al);

    cudaFuncSetAttribute(gemm_qkv, cudaFuncAttributeMaxDynamicSharedMemorySize, GEMM_SMEM);
    cudaFuncSetAttribute(gemm_out, cudaFuncAttributeMaxDynamicSharedMemorySize, GEMM_SMEM);
    cudaFuncSetAttribute(flash_mma, cudaFuncAttributeMaxDynamicSharedMemorySize, FLASH_SMEM);

    split_all<<<(N4_TOTAL + 255) / 256, 256>>>(x, Wq, Wk, Wv, Wo);

    gemm_qkv<<<dim3(HD / 128, S_LEN / 128, 3), 256, GEMM_SMEM>>>();

    flash_mma<<<dim3(S_LEN / 128, 16), 256, FLASH_SMEM>>>(Ah, Al);

    gemm_out<<<dim3(HD / 128, S_LEN / 128), 256, GEMM_SMEM>>>(out);
}

// round 12
// speedup vs baseline: 5.5732x; 1.1557x over previous
#include <cuda_runtime.h>
#include <cuda_fp16.h>
#include <math.h>
#include <cstdint>

#define S_LEN 2048
#define HD    1024
#define ALPHA_Q 0.1803368801111601f   // 0.125 * log2(e)

// ---------------------------------------------------------------------------
// Scratch (device globals) — fp16 scheme:
//   x: hi+lo.  Weights: fp16 only.  Q: hi+lo.  K, V: fp16.  A: hi+lo.
// ---------------------------------------------------------------------------
__device__ __align__(16) __half g_xh[S_LEN * HD], g_xl[S_LEN * HD];
__device__ __align__(16) __half g_wq[HD * HD], g_wk[HD * HD];
__device__ __align__(16) __half g_wv[HD * HD], g_wo[HD * HD];
__device__ __align__(16) __half g_Qh[S_LEN * HD], g_Ql[S_LEN * HD];
__device__ __align__(16) __half g_K[S_LEN * HD],  g_V[S_LEN * HD];
__device__ __align__(16) __half g_Ah[S_LEN * HD], g_Al[S_LEN * HD];

// ---------------------------------------------------------------------------
// Portable PTX helpers (sm_80-level, legal on bare sm_103)
// ---------------------------------------------------------------------------
__device__ __forceinline__ uint32_t smem_u32(const void* p) {
    uint32_t a;
    asm("{ .reg .u64 t; cvta.to.shared.u64 t, %1; cvt.u32.u64 %0, t; }"
        : "=r"(a) : "l"(p));
    return a;
}
__device__ __forceinline__ void cp_async16(uint32_t dst, const void* src) {
    asm volatile("cp.async.cg.shared.global [%0], [%1], 16;" :: "r"(dst), "l"(src));
}
__device__ __forceinline__ void cp_commit() {
    asm volatile("cp.async.commit_group;" ::: "memory");
}
template<int N> __device__ __forceinline__ void cp_wait() {
    asm volatile("cp.async.wait_group %0;" :: "n"(N) : "memory");
}
__device__ __forceinline__ void ldsm_x4(uint32_t* r, uint32_t a) {
    asm volatile("ldmatrix.sync.aligned.m8n8.x4.shared.b16 {%0,%1,%2,%3}, [%4];"
                 : "=r"(r[0]), "=r"(r[1]), "=r"(r[2]), "=r"(r[3]) : "r"(a));
}
__device__ __forceinline__ void ldsm_x4_t(uint32_t* r, uint32_t a) {
    asm volatile("ldmatrix.sync.aligned.m8n8.x4.trans.shared.b16 {%0,%1,%2,%3}, [%4];"
                 : "=r"(r[0]), "=r"(r[1]), "=r"(r[2]), "=r"(r[3]) : "r"(a));
}
__device__ __forceinline__ void mma_f16(float* c, const uint32_t* a, const uint32_t* b) {
    asm volatile(
        "mma.sync.aligned.m16n8k16.row.col.f32.f16.f16.f32 "
        "{%0,%1,%2,%3}, {%4,%5,%6,%7}, {%8,%9}, {%0,%1,%2,%3};"
        : "+f"(c[0]), "+f"(c[1]), "+f"(c[2]), "+f"(c[3])
        : "r"(a[0]), "r"(a[1]), "r"(a[2]), "r"(a[3]), "r"(b[0]), "r"(b[1]));
}
__device__ __forceinline__ float ex2(float x) {
    float r; asm("ex2.approx.f32 %0, %1;" : "=f"(r) : "f"(x)); return r;
}
// 128B-row swizzle; cb must be 16B aligned
__device__ __forceinline__ uint32_t swz(int row, int cb) {
    return (uint32_t)(row * 128 + (cb ^ ((row & 7) << 4)));
}
// pack two floats to f16x2 (x -> low half)
__device__ __forceinline__ uint32_t pack2h(float x, float y) {
    uint32_t r;
    asm("cvt.rn.f16x2.f32 %0, %1, %2;" : "=r"(r) : "f"(y), "f"(x));
    return r;
}
// two floats -> f16x2 hi + f16x2 lo (round-to-nearest split)
__device__ __forceinline__ void split2h(float x, float y, uint32_t& hi, uint32_t& lo) {
    hi = pack2h(x, y);
    __half2 h = *reinterpret_cast<__half2*>(&hi);
    float rx = x - __half2float(h.x);
    float ry = y - __half2float(h.y);
    lo = pack2h(rx, ry);
}

// ---------------------------------------------------------------------------
// Fused conversion: x -> fp16 hi/lo ; Wq/Wk/Wv/Wo -> fp16 — ONE launch.
// ---------------------------------------------------------------------------
#define N4_X 524288
#define N4_W 262144
#define N4_TOTAL (N4_X + 4 * N4_W)

__global__ void __launch_bounds__(256)
split_all(const float* __restrict__ x,  const float* __restrict__ Wq,
          const float* __restrict__ Wk, const float* __restrict__ Wv,
          const float* __restrict__ Wo)
{
    int i = blockIdx.x * blockDim.x + threadIdx.x;
    if (i >= N4_TOTAL) return;
    int j = i;
    if (j < N4_X) {
        float4 v = ((const float4*)x)[j];
        uint32_t h0, l0, h1, l1;
        split2h(v.x, v.y, h0, l0);
        split2h(v.z, v.w, h1, l1);
        ((uint32_t*)g_xh)[2 * j + 0] = h0;
        ((uint32_t*)g_xh)[2 * j + 1] = h1;
        ((uint32_t*)g_xl)[2 * j + 0] = l0;
        ((uint32_t*)g_xl)[2 * j + 1] = l1;
        return;
    }
    j -= N4_X;
    const float* in;
    __half* w;
    if (j < N4_W)      { in = Wq; w = g_wq; }
    else if ((j -= N4_W) < N4_W) { in = Wk; w = g_wk; }
    else if ((j -= N4_W) < N4_W) { in = Wv; w = g_wv; }
    else               { j -= N4_W; in = Wo; w = g_wo; }
    float4 v = ((const float4*)in)[j];
    ((uint32_t*)w)[2 * j + 0] = pack2h(v.x, v.y);
    ((uint32_t*)w)[2 * j + 1] = pack2h(v.z, v.w);
}

// ---------------------------------------------------------------------------
// Split-GEMM core: C = (Ah + Al) * B^T, merged sections per chunk (R11 form).
// Block 128x128, BK=64, 8 warps, double-buffered.
// ---------------------------------------------------------------------------
#define G_STAGE 49152
#define GEMM_SMEM (2 * G_STAGE)    // 98304
#define NCHUNK 16

__device__ __forceinline__ void gemm_core(
    uint32_t sb,
    const __half* Ah, const __half* Al, const __half* B,
    __half* outHi, __half* outLo, float* outF,
    float alpha, int m0, int n0)
{
    const int tid = threadIdx.x;
    const int lane = tid & 31, wid = tid >> 5;
    const int wm = wid & 3, wn = wid >> 2;

    float c[2][8][4];
#pragma unroll
    for (int mt = 0; mt < 2; mt++)
#pragma unroll
        for (int nt = 0; nt < 8; nt++)
#pragma unroll
            for (int j = 0; j < 4; j++) c[mt][nt][j] = 0.f;

    auto issue = [&](int ck, int stage) {
        size_t ko = (size_t)ck * 128;            // bytes into each 2048B row
        uint32_t dAh = sb + stage * G_STAGE;
        uint32_t dAl = dAh + 16384;
        uint32_t dB  = dAh + 32768;
#pragma unroll
        for (int i = 0; i < 4; i++) {
            int lin = tid + i * 256;
            int row = lin >> 3, cb = (lin & 7) << 4;
            size_t goA = (size_t)(m0 + row) * 2048 + ko + cb;
            cp_async16(dAh + swz(row, cb), (const char*)Ah + goA);
            cp_async16(dAl + swz(row, cb), (const char*)Al + goA);
            cp_async16(dB + swz(row, cb),
                       (const char*)B + (size_t)(n0 + row) * 2048 + ko + cb);
        }
        cp_commit();
    };

    issue(0, 0);
    issue(1, 1);

    for (int ck = 0; ck < NCHUNK; ck++) {
        if (ck == NCHUNK - 1) cp_wait<0>(); else cp_wait<1>();
        __syncthreads();
        uint32_t aH = sb + (ck & 1) * G_STAGE;
        uint32_t aL = aH + 16384;
        uint32_t bB = aH + 32768;
#pragma unroll
        for (int kk = 0; kk < 4; kk++) {
            uint32_t afh[2][4], afl[2][4], bfr[8][2];
#pragma unroll
            for (int mt = 0; mt < 2; mt++) {
                int row = wm * 32 + mt * 16 + (lane & 15);
                int cb = kk * 32 + ((lane & 16) ? 16 : 0);
                ldsm_x4(afh[mt], aH + swz(row, cb));
                ldsm_x4(afl[mt], aL + swz(row, cb));
            }
#pragma unroll
            for (int ng = 0; ng < 4; ng++) {
                uint32_t t[4];
                int row = wn * 64 + ng * 16 + (lane & 7) + ((lane & 16) ? 8 : 0);
                int cb = kk * 32 + ((lane & 8) ? 16 : 0);
                ldsm_x4(t, bB + swz(row, cb));
                bfr[2 * ng][0] = t[0];     bfr[2 * ng][1] = t[1];
                bfr[2 * ng + 1][0] = t[2]; bfr[2 * ng + 1][1] = t[3];
            }
#pragma unroll
            for (int mt = 0; mt < 2; mt++)
#pragma unroll
                for (int nt = 0; nt < 8; nt++) {
                    mma_f16(c[mt][nt], afh[mt], bfr[nt]);
                    mma_f16(c[mt][nt], afl[mt], bfr[nt]);
                }
        }
        __syncthreads();
        if (ck + 2 < NCHUNK) issue(ck + 2, ck & 1);
    }

    const int gid = lane >> 2, t2 = (lane & 3) * 2;
#pragma unroll
    for (int mt = 0; mt < 2; mt++)
#pragma unroll
        for (int hh = 0; hh < 2; hh++) {
            int row = m0 + wm * 32 + mt * 16 + gid + hh * 8;
#pragma unroll
            for (int nt = 0; nt < 8; nt++) {
                int col = n0 + wn * 64 + nt * 8 + t2;
                float v0 = c[mt][nt][2 * hh] * alpha;
                float v1 = c[mt][nt][2 * hh + 1] * alpha;
                size_t idx = (size_t)row * 1024 + col;
                if (outF) {
                    *(float2*)(outF + idx) = make_float2(v0, v1);
                } else if (outLo) {
                    uint32_t hb, lb;
                    split2h(v0, v1, hb, lb);
                    ((uint32_t*)outHi)[idx >> 1] = hb;
                    ((uint32_t*)outLo)[idx >> 1] = lb;
                } else {
                    ((uint32_t*)outHi)[idx >> 1] = pack2h(v0, v1);
                }
            }
        }
}

// Fused Q/K/V projections: blockIdx.z selects weight + destination.
__global__ void __launch_bounds__(256)
gemm_qkv()
{
    extern __shared__ __align__(128) char sm_g[];
    const uint32_t sb = smem_u32(sm_g);
    const int m0 = blockIdx.y * 128, n0 = blockIdx.x * 128;
    const int z = blockIdx.z;
    if (z == 0)
        gemm_core(sb, g_xh, g_xl, g_wq, g_Qh, g_Ql, nullptr, (float)ALPHA_Q, m0, n0);
    else if (z == 1)
        gemm_core(sb, g_xh, g_xl, g_wk, g_K, nullptr, nullptr, 1.0f, m0, n0);
    else
        gemm_core(sb, g_xh, g_xl, g_wv, g_V, nullptr, nullptr, 1.0f, m0, n0);
}

// Output projection: A (hi/lo) x Wo -> fp32 out.
__global__ void __launch_bounds__(256)
gemm_out(float* __restrict__ out)
{
    extern __shared__ __align__(128) char sm_g[];
    const uint32_t sb = smem_u32(sm_g);
    gemm_core(sb, g_Ah, g_Al, g_wo, nullptr, nullptr, out, 1.0f,
              blockIdx.y * 128, blockIdx.x * 128);
}

// ---------------------------------------------------------------------------
// Flash attention, fp16 mma, double-buffered K/V.
// R12: P·V single-term (P plain fp16, Pl dropped: -25% MMAs) and
// __launch_bounds__(256,2) for 2 CTAs/SM (64KB smem x2 = 128KB).
// ---------------------------------------------------------------------------
#define SQH 0
#define SQL 16384
#define SKV0 32768
#define KV_STAGE 16384
#define OK 0
#define OV 8192
#define FLASH_SMEM (32768 + 2 * KV_STAGE)   // 65536

__global__ void __launch_bounds__(256, 2)
flash_mma(__half* __restrict__ Ah_, __half* __restrict__ Al_)
{
    extern __shared__ __align__(128) char sm_f[];
    const uint32_t sb = smem_u32(sm_f);
    const int tid = threadIdx.x, lane = tid & 31, w = tid >> 5;
    const int h = blockIdx.y, q0 = blockIdx.x * 128;

    auto ldKV = [&](int kt) {
        uint32_t st = sb + SKV0 + (uint32_t)(kt & 1) * KV_STAGE;
        size_t kr = (size_t)kt * 64;
#pragma unroll
        for (int i = 0; i < 2; i++) {
            int lin = tid + i * 256;
            int row = lin >> 3, cb = (lin & 7) << 4;
            size_t go = (kr + row) * 2048 + (size_t)h * 128 + cb;
            uint32_t so = swz(row, cb);
            cp_async16(st + OK + so, (const char*)g_K + go);
            cp_async16(st + OV + so, (const char*)g_V + go);
        }
        cp_commit();
    };

#pragma unroll
    for (int i = 0; i < 4; i++) {
        int lin = tid + i * 256;
        int row = lin >> 3, cb = (lin & 7) << 4;
        size_t go = (size_t)(q0 + row) * 2048 + (size_t)h * 128 + cb;
        cp_async16(sb + SQH + swz(row, cb), (const char*)g_Qh + go);
        cp_async16(sb + SQL + swz(row, cb), (const char*)g_Ql + go);
    }
    cp_commit();
    ldKV(0);
    ldKV(1);

    cp_wait<2>();
    __syncthreads();

    uint32_t qh[4][4], ql[4][4];
    {
        int row = w * 16 + (lane & 15);
#pragma unroll
        for (int kk = 0; kk < 4; kk++) {
            int cb = kk * 32 + ((lane & 16) ? 16 : 0);
            ldsm_x4(qh[kk], sb + SQH + swz(row, cb));
            ldsm_x4(ql[kk], sb + SQL + swz(row, cb));
        }
    }

    float m0v = -INFINITY, m1v = -INFINITY, l0v = 0.f, l1v = 0.f;
    float o[8][4];
#pragma unroll
    for (int d = 0; d < 8; d++)
#pragma unroll
        for (int j = 0; j < 4; j++) o[d][j] = 0.f;

    for (int kt = 0; kt < 32; kt++) {
        if (kt == 31) cp_wait<0>(); else cp_wait<1>();
        __syncthreads();
        const uint32_t st = sb + SKV0 + (uint32_t)(kt & 1) * KV_STAGE;

        float c[8][4];
#pragma unroll
        for (int nt = 0; nt < 8; nt++)
#pragma unroll
            for (int j = 0; j < 4; j++) c[nt][j] = 0.f;

#pragma unroll
        for (int kk = 0; kk < 4; kk++) {
#pragma unroll
            for (int ng = 0; ng < 4; ng++) {
                uint32_t bh[4];
                int row = ng * 16 + (lane & 7) + ((lane & 16) ? 8 : 0);
                int cb = kk * 32 + ((lane & 8) ? 16 : 0);
                ldsm_x4(bh, st + OK + swz(row, cb));
                mma_f16(c[2 * ng],     qh[kk], bh);
                mma_f16(c[2 * ng],     ql[kk], bh);
                mma_f16(c[2 * ng + 1], qh[kk], bh + 2);
                mma_f16(c[2 * ng + 1], ql[kk], bh + 2);
            }
        }

        float mx0 = -INFINITY, mx1 = -INFINITY;
#pragma unroll
        for (int nt = 0; nt < 8; nt++) {
            mx0 = fmaxf(mx0, fmaxf(c[nt][0], c[nt][1]));
            mx1 = fmaxf(mx1, fmaxf(c[nt][2], c[nt][3]));
        }
        mx0 = fmaxf(mx0, __shfl_xor_sync(0xffffffffu, mx0, 1));
        mx0 = fmaxf(mx0, __shfl_xor_sync(0xffffffffu, mx0, 2));
        mx1 = fmaxf(mx1, __shfl_xor_sync(0xffffffffu, mx1, 1));
        mx1 = fmaxf(mx1, __shfl_xor_sync(0xffffffffu, mx1, 2));
        float mn0 = fmaxf(m0v, mx0), mn1 = fmaxf(m1v, mx1);
        float cor0 = ex2(m0v - mn0), cor1 = ex2(m1v - mn1);
        float rs0 = 0.f, rs1 = 0.f;
#pragma unroll
        for (int nt = 0; nt < 8; nt++) {
            c[nt][0] = ex2(c[nt][0] - mn0);
            c[nt][1] = ex2(c[nt][1] - mn0);
            c[nt][2] = ex2(c[nt][2] - mn1);
            c[nt][3] = ex2(c[nt][3] - mn1);
            rs0 += c[nt][0] + c[nt][1];
            rs1 += c[nt][2] + c[nt][3];
        }
        rs0 += __shfl_xor_sync(0xffffffffu, rs0, 1);
        rs0 += __shfl_xor_sync(0xffffffffu, rs0, 2);
        rs1 += __shfl_xor_sync(0xffffffffu, rs1, 1);
        rs1 += __shfl_xor_sync(0xffffffffu, rs1, 2);
        l0v = l0v * cor0 + rs0;
        l1v = l1v * cor1 + rs1;
        m0v = mn0; m1v = mn1;
#pragma unroll
        for (int d = 0; d < 8; d++) {
            o[d][0] *= cor0; o[d][1] *= cor0;
            o[d][2] *= cor1; o[d][3] *= cor1;
        }

        // ---- O += P V (P plain fp16; single term), V via ldmatrix.trans ----
#pragma unroll
        for (int kk = 0; kk < 4; kk++) {
            uint32_t ah[4];
            ah[0] = pack2h(c[2 * kk][0],     c[2 * kk][1]);
            ah[1] = pack2h(c[2 * kk][2],     c[2 * kk][3]);
            ah[2] = pack2h(c[2 * kk + 1][0], c[2 * kk + 1][1]);
            ah[3] = pack2h(c[2 * kk + 1][2], c[2 * kk + 1][3]);
            int row = kk * 16 + (lane & 15);
#pragma unroll
            for (int dg = 0; dg < 4; dg++) {
                uint32_t bh[4];
                int cb = dg * 32 + ((lane & 16) ? 16 : 0);
                ldsm_x4_t(bh, st + OV + swz(row, cb));
                mma_f16(o[2 * dg],     ah, bh);
                mma_f16(o[2 * dg + 1], ah, bh + 2);
            }
        }
        __syncthreads();
        if (kt + 2 < 32) ldKV(kt + 2);
    }

    float inv0 = 1.f / l0v, inv1 = 1.f / l1v;
    const int gid = lane >> 2, t2 = (lane & 3) * 2;
    int r0 = q0 + w * 16 + gid;
#pragma unroll
    for (int d = 0; d < 8; d++) {
        int col = h * 64 + d * 8 + t2;
        uint32_t hb, lb;
        size_t i0 = ((size_t)r0 * 1024 + col) >> 1;
        split2h(o[d][0] * inv0, o[d][1] * inv0, hb, lb);
        ((uint32_t*)Ah_)[i0] = hb;
        ((uint32_t*)Al_)[i0] = lb;
        size_t i1 = ((size_t)(r0 + 8) * 1024 + col) >> 1;
        split2h(o[d][2] * inv1, o[d][3] * inv1, hb, lb);
        ((uint32_t*)Ah_)[i1] = hb;
        ((uint32_t*)Al_)[i1] = lb;
    }
}

// ---------------------------------------------------------------------------
// Launch
// ---------------------------------------------------------------------------
extern "C" void kernel_launch(void* const* d_in, const int* in_sizes, int n_in,
                              void* d_out, int out_size)
{
    (void)in_sizes; (void)n_in; (void)out_size;
    const float* x  = (const float*)d_in[0];
    const float* Wq = (const float*)d_in[1];
    const float* Wk = (const float*)d_in[2];
    const float* Wv = (const float*)d_in[3];
    const float* Wo = (const float*)d_in[4];
    float* out = (float*)d_out;

    __half *Ah, *Al;
    cudaGetSymbolAddress((void**)&Ah, g_Ah);
    cudaGetSymbolAddress((void**)&Al, g_Al);

    cudaFuncSetAttribute(gemm_qkv, cudaFuncAttributeMaxDynamicSharedMemorySize, GEMM_SMEM);
    cudaFuncSetAttribute(gemm_out, cudaFuncAttributeMaxDynamicSharedMemorySize, GEMM_SMEM);
    cudaFuncSetAttribute(flash_mma, cudaFuncAttributeMaxDynamicSharedMemorySize, FLASH_SMEM);

    split_all<<<(N4_TOTAL + 255) / 256, 256>>>(x, Wq, Wk, Wv, Wo);

    gemm_qkv<<<dim3(HD / 128, S_LEN / 128, 3), 256, GEMM_SMEM>>>();

    flash_mma<<<dim3(S_LEN / 128, 16), 256, FLASH_SMEM>>>(Ah, Al);

    gemm_out<<<dim3(HD / 128, S_LEN / 128), 256, GEMM_SMEM>>>(out);
}

// round 14
// speedup vs baseline: 5.7160x; 1.0256x over previous
#include <cuda_runtime.h>
#include <cuda_fp16.h>
#include <math.h>
#include <cstdint>

#define S_LEN 2048
#define HD    1024
#define ALPHA_Q 0.1803368801111601f   // 0.125 * log2(e)

// ---------------------------------------------------------------------------
// Scratch (device globals) — fp16 scheme:
//   x: hi+lo.  Weights: fp16 only.  Q: hi+lo.  K, V: fp16.  A: hi+lo.
// ---------------------------------------------------------------------------
__device__ __align__(16) __half g_xh[S_LEN * HD], g_xl[S_LEN * HD];
__device__ __align__(16) __half g_wq[HD * HD], g_wk[HD * HD];
__device__ __align__(16) __half g_wv[HD * HD], g_wo[HD * HD];
__device__ __align__(16) __half g_Qh[S_LEN * HD], g_Ql[S_LEN * HD];
__device__ __align__(16) __half g_K[S_LEN * HD],  g_V[S_LEN * HD];
__device__ __align__(16) __half g_Ah[S_LEN * HD], g_Al[S_LEN * HD];

// ---------------------------------------------------------------------------
// Portable PTX helpers (sm_80-level, legal on bare sm_103)
// ---------------------------------------------------------------------------
__device__ __forceinline__ uint32_t smem_u32(const void* p) {
    uint32_t a;
    asm("{ .reg .u64 t; cvta.to.shared.u64 t, %1; cvt.u32.u64 %0, t; }"
        : "=r"(a) : "l"(p));
    return a;
}
__device__ __forceinline__ void cp_async16(uint32_t dst, const void* src) {
    asm volatile("cp.async.cg.shared.global [%0], [%1], 16;" :: "r"(dst), "l"(src));
}
__device__ __forceinline__ void cp_commit() {
    asm volatile("cp.async.commit_group;" ::: "memory");
}
template<int N> __device__ __forceinline__ void cp_wait() {
    asm volatile("cp.async.wait_group %0;" :: "n"(N) : "memory");
}
__device__ __forceinline__ void ldsm_x4(uint32_t* r, uint32_t a) {
    asm volatile("ldmatrix.sync.aligned.m8n8.x4.shared.b16 {%0,%1,%2,%3}, [%4];"
                 : "=r"(r[0]), "=r"(r[1]), "=r"(r[2]), "=r"(r[3]) : "r"(a));
}
__device__ __forceinline__ void ldsm_x4_t(uint32_t* r, uint32_t a) {
    asm volatile("ldmatrix.sync.aligned.m8n8.x4.trans.shared.b16 {%0,%1,%2,%3}, [%4];"
                 : "=r"(r[0]), "=r"(r[1]), "=r"(r[2]), "=r"(r[3]) : "r"(a));
}
__device__ __forceinline__ void mma_f16(float* c, const uint32_t* a, const uint32_t* b) {
    asm volatile(
        "mma.sync.aligned.m16n8k16.row.col.f32.f16.f16.f32 "
        "{%0,%1,%2,%3}, {%4,%5,%6,%7}, {%8,%9}, {%0,%1,%2,%3};"
        : "+f"(c[0]), "+f"(c[1]), "+f"(c[2]), "+f"(c[3])
        : "r"(a[0]), "r"(a[1]), "r"(a[2]), "r"(a[3]), "r"(b[0]), "r"(b[1]));
}
__device__ __forceinline__ float ex2(float x) {
    float r; asm("ex2.approx.f32 %0, %1;" : "=f"(r) : "f"(x)); return r;
}
// 128B-row swizzle; cb must be 16B aligned
__device__ __forceinline__ uint32_t swz(int row, int cb) {
    return (uint32_t)(row * 128 + (cb ^ ((row & 7) << 4)));
}
// pack two floats to f16x2 (x -> low half)
__device__ __forceinline__ uint32_t pack2h(float x, float y) {
    uint32_t r;
    asm("cvt.rn.f16x2.f32 %0, %1, %2;" : "=r"(r) : "f"(y), "f"(x));
    return r;
}
// two floats -> f16x2 hi + f16x2 lo (round-to-nearest split)
__device__ __forceinline__ void split2h(float x, float y, uint32_t& hi, uint32_t& lo) {
    hi = pack2h(x, y);
    __half2 h = *reinterpret_cast<__half2*>(&hi);
    float rx = x - __half2float(h.x);
    float ry = y - __half2float(h.y);
    lo = pack2h(rx, ry);
}

// ---------------------------------------------------------------------------
// Fused conversion: x -> fp16 hi/lo ; Wq/Wk/Wv/Wo -> fp16 — ONE launch.
// ---------------------------------------------------------------------------
#define N4_X 524288
#define N4_W 262144
#define N4_TOTAL (N4_X + 4 * N4_W)

__global__ void __launch_bounds__(256)
split_all(const float* __restrict__ x,  const float* __restrict__ Wq,
          const float* __restrict__ Wk, const float* __restrict__ Wv,
          const float* __restrict__ Wo)
{
    int i = blockIdx.x * blockDim.x + threadIdx.x;
    if (i >= N4_TOTAL) return;
    int j = i;
    if (j < N4_X) {
        float4 v = ((const float4*)x)[j];
        uint32_t h0, l0, h1, l1;
        split2h(v.x, v.y, h0, l0);
        split2h(v.z, v.w, h1, l1);
        ((uint32_t*)g_xh)[2 * j + 0] = h0;
        ((uint32_t*)g_xh)[2 * j + 1] = h1;
        ((uint32_t*)g_xl)[2 * j + 0] = l0;
        ((uint32_t*)g_xl)[2 * j + 1] = l1;
        return;
    }
    j -= N4_X;
    const float* in;
    __half* w;
    if (j < N4_W)      { in = Wq; w = g_wq; }
    else if ((j -= N4_W) < N4_W) { in = Wk; w = g_wk; }
    else if ((j -= N4_W) < N4_W) { in = Wv; w = g_wv; }
    else               { j -= N4_W; in = Wo; w = g_wo; }
    float4 v = ((const float4*)in)[j];
    ((uint32_t*)w)[2 * j + 0] = pack2h(v.x, v.y);
    ((uint32_t*)w)[2 * j + 1] = pack2h(v.z, v.w);
}

// ---------------------------------------------------------------------------
// Split-GEMM core: C = (Ah + Al) * B^T, merged sections per chunk.
// Block 128x128, BK=64, 8 warps, double-buffered, 2 CTAs/SM.
// ---------------------------------------------------------------------------
#define G_STAGE 49152
#define GEMM_SMEM (2 * G_STAGE)    // 98304
#define NCHUNK 16

__device__ __forceinline__ void gemm_core(
    uint32_t sb,
    const __half* Ah, const __half* Al, const __half* B,
    __half* outHi, __half* outLo, float* outF,
    float alpha, int m0, int n0)
{
    const int tid = threadIdx.x;
    const int lane = tid & 31, wid = tid >> 5;
    const int wm = wid & 3, wn = wid >> 2;

    float c[2][8][4];
#pragma unroll
    for (int mt = 0; mt < 2; mt++)
#pragma unroll
        for (int nt = 0; nt < 8; nt++)
#pragma unroll
            for (int j = 0; j < 4; j++) c[mt][nt][j] = 0.f;

    auto issue = [&](int ck, int stage) {
        size_t ko = (size_t)ck * 128;            // bytes into each 2048B row
        uint32_t dAh = sb + stage * G_STAGE;
        uint32_t dAl = dAh + 16384;
        uint32_t dB  = dAh + 32768;
#pragma unroll
        for (int i = 0; i < 4; i++) {
            int lin = tid + i * 256;
            int row = lin >> 3, cb = (lin & 7) << 4;
            size_t goA = (size_t)(m0 + row) * 2048 + ko + cb;
            cp_async16(dAh + swz(row, cb), (const char*)Ah + goA);
            cp_async16(dAl + swz(row, cb), (const char*)Al + goA);
            cp_async16(dB + swz(row, cb),
                       (const char*)B + (size_t)(n0 + row) * 2048 + ko + cb);
        }
        cp_commit();
    };

    issue(0, 0);
    issue(1, 1);

    for (int ck = 0; ck < NCHUNK; ck++) {
        if (ck == NCHUNK - 1) cp_wait<0>(); else cp_wait<1>();
        __syncthreads();
        uint32_t aH = sb + (ck & 1) * G_STAGE;
        uint32_t aL = aH + 16384;
        uint32_t bB = aH + 32768;
#pragma unroll
        for (int kk = 0; kk < 4; kk++) {
            uint32_t afh[2][4], afl[2][4], bfr[8][2];
#pragma unroll
            for (int mt = 0; mt < 2; mt++) {
                int row = wm * 32 + mt * 16 + (lane & 15);
                int cb = kk * 32 + ((lane & 16) ? 16 : 0);
                ldsm_x4(afh[mt], aH + swz(row, cb));
                ldsm_x4(afl[mt], aL + swz(row, cb));
            }
#pragma unroll
            for (int ng = 0; ng < 4; ng++) {
                uint32_t t[4];
                int row = wn * 64 + ng * 16 + (lane & 7) + ((lane & 16) ? 8 : 0);
                int cb = kk * 32 + ((lane & 8) ? 16 : 0);
                ldsm_x4(t, bB + swz(row, cb));
                bfr[2 * ng][0] = t[0];     bfr[2 * ng][1] = t[1];
                bfr[2 * ng + 1][0] = t[2]; bfr[2 * ng + 1][1] = t[3];
            }
#pragma unroll
            for (int mt = 0; mt < 2; mt++)
#pragma unroll
                for (int nt = 0; nt < 8; nt++) {
                    mma_f16(c[mt][nt], afh[mt], bfr[nt]);
                    mma_f16(c[mt][nt], afl[mt], bfr[nt]);
                }
        }
        __syncthreads();
        if (ck + 2 < NCHUNK) issue(ck + 2, ck & 1);
    }

    const int gid = lane >> 2, t2 = (lane & 3) * 2;
#pragma unroll
    for (int mt = 0; mt < 2; mt++)
#pragma unroll
        for (int hh = 0; hh < 2; hh++) {
            int row = m0 + wm * 32 + mt * 16 + gid + hh * 8;
#pragma unroll
            for (int nt = 0; nt < 8; nt++) {
                int col = n0 + wn * 64 + nt * 8 + t2;
                float v0 = c[mt][nt][2 * hh] * alpha;
                float v1 = c[mt][nt][2 * hh + 1] * alpha;
                size_t idx = (size_t)row * 1024 + col;
                if (outF) {
                    *(float2*)(outF + idx) = make_float2(v0, v1);
                } else if (outLo) {
                    uint32_t hb, lb;
                    split2h(v0, v1, hb, lb);
                    ((uint32_t*)outHi)[idx >> 1] = hb;
                    ((uint32_t*)outLo)[idx >> 1] = lb;
                } else {
                    ((uint32_t*)outHi)[idx >> 1] = pack2h(v0, v1);
                }
            }
        }
}

// Fused Q/K/V projections: blockIdx.z selects weight + destination.
__global__ void __launch_bounds__(256, 2)
gemm_qkv()
{
    extern __shared__ __align__(128) char sm_g[];
    const uint32_t sb = smem_u32(sm_g);
    const int m0 = blockIdx.y * 128, n0 = blockIdx.x * 128;
    const int z = blockIdx.z;
    if (z == 0)
        gemm_core(sb, g_xh, g_xl, g_wq, g_Qh, g_Ql, nullptr, (float)ALPHA_Q, m0, n0);
    else if (z == 1)
        gemm_core(sb, g_xh, g_xl, g_wk, g_K, nullptr, nullptr, 1.0f, m0, n0);
    else
        gemm_core(sb, g_xh, g_xl, g_wv, g_V, nullptr, nullptr, 1.0f, m0, n0);
}

// Output projection: A (hi/lo) x Wo -> fp32 out.
__global__ void __launch_bounds__(256, 2)
gemm_out(float* __restrict__ out)
{
    extern __shared__ __align__(128) char sm_g[];
    const uint32_t sb = smem_u32(sm_g);
    gemm_core(sb, g_Ah, g_Al, g_wo, nullptr, nullptr, out, 1.0f,
              blockIdx.y * 128, blockIdx.x * 128);
}

// ---------------------------------------------------------------------------
// Flash attention, fp16 mma, double-buffered K/V, 2 CTAs/SM.
// P·V single-term (P plain fp16).
// ---------------------------------------------------------------------------
#define SQH 0
#define SQL 16384
#define SKV0 32768
#define KV_STAGE 16384
#define OK 0
#define OV 8192
#define FLASH_SMEM (32768 + 2 * KV_STAGE)   // 65536

__global__ void __launch_bounds__(256, 2)
flash_mma(__half* __restrict__ Ah_, __half* __restrict__ Al_)
{
    extern __shared__ __align__(128) char sm_f[];
    const uint32_t sb = smem_u32(sm_f);
    const int tid = threadIdx.x, lane = tid & 31, w = tid >> 5;
    const int h = blockIdx.y, q0 = blockIdx.x * 128;

    auto ldKV = [&](int kt) {
        uint32_t st = sb + SKV0 + (uint32_t)(kt & 1) * KV_STAGE;
        size_t kr = (size_t)kt * 64;
#pragma unroll
        for (int i = 0; i < 2; i++) {
            int lin = tid + i * 256;
            int row = lin >> 3, cb = (lin & 7) << 4;
            size_t go = (kr + row) * 2048 + (size_t)h * 128 + cb;
            uint32_t so = swz(row, cb);
            cp_async16(st + OK + so, (const char*)g_K + go);
            cp_async16(st + OV + so, (const char*)g_V + go);
        }
        cp_commit();
    };

#pragma unroll
    for (int i = 0; i < 4; i++) {
        int lin = tid + i * 256;
        int row = lin >> 3, cb = (lin & 7) << 4;
        size_t go = (size_t)(q0 + row) * 2048 + (size_t)h * 128 + cb;
        cp_async16(sb + SQH + swz(row, cb), (const char*)g_Qh + go);
        cp_async16(sb + SQL + swz(row, cb), (const char*)g_Ql + go);
    }
    cp_commit();
    ldKV(0);
    ldKV(1);

    cp_wait<2>();
    __syncthreads();

    uint32_t qh[4][4], ql[4][4];
    {
        int row = w * 16 + (lane & 15);
#pragma unroll
        for (int kk = 0; kk < 4; kk++) {
            int cb = kk * 32 + ((lane & 16) ? 16 : 0);
            ldsm_x4(qh[kk], sb + SQH + swz(row, cb));
            ldsm_x4(ql[kk], sb + SQL + swz(row, cb));
        }
    }

    float m0v = -INFINITY, m1v = -INFINITY, l0v = 0.f, l1v = 0.f;
    float o[8][4];
#pragma unroll
    for (int d = 0; d < 8; d++)
#pragma unroll
        for (int j = 0; j < 4; j++) o[d][j] = 0.f;

    for (int kt = 0; kt < 32; kt++) {
        if (kt == 31) cp_wait<0>(); else cp_wait<1>();
        __syncthreads();
        const uint32_t st = sb + SKV0 + (uint32_t)(kt & 1) * KV_STAGE;

        float c[8][4];
#pragma unroll
        for (int nt = 0; nt < 8; nt++)
#pragma unroll
            for (int j = 0; j < 4; j++) c[nt][j] = 0.f;

#pragma unroll
        for (int kk = 0; kk < 4; kk++) {
#pragma unroll
            for (int ng = 0; ng < 4; ng++) {
                uint32_t bh[4];
                int row = ng * 16 + (lane & 7) + ((lane & 16) ? 8 : 0);
                int cb = kk * 32 + ((lane & 8) ? 16 : 0);
                ldsm_x4(bh, st + OK + swz(row, cb));
                mma_f16(c[2 * ng],     qh[kk], bh);
                mma_f16(c[2 * ng],     ql[kk], bh);
                mma_f16(c[2 * ng + 1], qh[kk], bh + 2);
                mma_f16(c[2 * ng + 1], ql[kk], bh + 2);
            }
        }

        float mx0 = -INFINITY, mx1 = -INFINITY;
#pragma unroll
        for (int nt = 0; nt < 8; nt++) {
            mx0 = fmaxf(mx0, fmaxf(c[nt][0], c[nt][1]));
            mx1 = fmaxf(mx1, fmaxf(c[nt][2], c[nt][3]));
        }
        mx0 = fmaxf(mx0, __shfl_xor_sync(0xffffffffu, mx0, 1));
        mx0 = fmaxf(mx0, __shfl_xor_sync(0xffffffffu, mx0, 2));
        mx1 = fmaxf(mx1, __shfl_xor_sync(0xffffffffu, mx1, 1));
        mx1 = fmaxf(mx1, __shfl_xor_sync(0xffffffffu, mx1, 2));
        float mn0 = fmaxf(m0v, mx0), mn1 = fmaxf(m1v, mx1);
        float cor0 = ex2(m0v - mn0), cor1 = ex2(m1v - mn1);
        float rs0 = 0.f, rs1 = 0.f;
#pragma unroll
        for (int nt = 0; nt < 8; nt++) {
            c[nt][0] = ex2(c[nt][0] - mn0);
            c[nt][1] = ex2(c[nt][1] - mn0);
            c[nt][2] = ex2(c[nt][2] - mn1);
            c[nt][3] = ex2(c[nt][3] - mn1);
            rs0 += c[nt][0] + c[nt][1];
            rs1 += c[nt][2] + c[nt][3];
        }
        rs0 += __shfl_xor_sync(0xffffffffu, rs0, 1);
        rs0 += __shfl_xor_sync(0xffffffffu, rs0, 2);
        rs1 += __shfl_xor_sync(0xffffffffu, rs1, 1);
        rs1 += __shfl_xor_sync(0xffffffffu, rs1, 2);
        l0v = l0v * cor0 + rs0;
        l1v = l1v * cor1 + rs1;
        m0v = mn0; m1v = mn1;
#pragma unroll
        for (int d = 0; d < 8; d++) {
            o[d][0] *= cor0; o[d][1] *= cor0;
            o[d][2] *= cor1; o[d][3] *= cor1;
        }

        // ---- O += P V (P plain fp16; single term), V via ldmatrix.trans ----
#pragma unroll
        for (int kk = 0; kk < 4; kk++) {
            uint32_t ah[4];
            ah[0] = pack2h(c[2 * kk][0],     c[2 * kk][1]);
            ah[1] = pack2h(c[2 * kk][2],     c[2 * kk][3]);
            ah[2] = pack2h(c[2 * kk + 1][0], c[2 * kk + 1][1]);
            ah[3] = pack2h(c[2 * kk + 1][2], c[2 * kk + 1][3]);
            int row = kk * 16 + (lane & 15);
#pragma unroll
            for (int dg = 0; dg < 4; dg++) {
                uint32_t bh[4];
                int cb = dg * 32 + ((lane & 16) ? 16 : 0);
                ldsm_x4_t(bh, st + OV + swz(row, cb));
                mma_f16(o[2 * dg],     ah, bh);
                mma_f16(o[2 * dg + 1], ah, bh + 2);
            }
        }
        __syncthreads();
        if (kt + 2 < 32) ldKV(kt + 2);
    }

    float inv0 = 1.f / l0v, inv1 = 1.f / l1v;
    const int gid = lane >> 2, t2 = (lane & 3) * 2;
    int r0 = q0 + w * 16 + gid;
#pragma unroll
    for (int d = 0; d < 8; d++) {
        int col = h * 64 + d * 8 + t2;
        uint32_t hb, lb;
        size_t i0 = ((size_t)r0 * 1024 + col) >> 1;
        split2h(o[d][0] * inv0, o[d][1] * inv0, hb, lb);
        ((uint32_t*)Ah_)[i0] = hb;
        ((uint32_t*)Al_)[i0] = lb;
        size_t i1 = ((size_t)(r0 + 8) * 1024 + col) >> 1;
        split2h(o[d][2] * inv1, o[d][3] * inv1, hb, lb);
        ((uint32_t*)Ah_)[i1] = hb;
        ((uint32_t*)Al_)[i1] = lb;
    }
}

// ---------------------------------------------------------------------------
// Launch
// ---------------------------------------------------------------------------
extern "C" void kernel_launch(void* const* d_in, const int* in_sizes, int n_in,
                              void* d_out, int out_size)
{
    (void)in_sizes; (void)n_in; (void)out_size;
    const float* x  = (const float*)d_in[0];
    const float* Wq = (const float*)d_in[1];
    const float* Wk = (const float*)d_in[2];
    const float* Wv = (const float*)d_in[3];
    const float* Wo = (const float*)d_in[4];
    float* out = (float*)d_out;

    __half *Ah, *Al;
    cudaGetSymbolAddress((void**)&Ah, g_Ah);
    cudaGetSymbolAddress((void**)&Al, g_Al);

    cudaFuncSetAttribute(gemm_qkv, cudaFuncAttributeMaxDynamicSharedMemorySize, GEMM_SMEM);
    cudaFuncSetAttribute(gemm_out, cudaFuncAttributeMaxDynamicSharedMemorySize, GEMM_SMEM);
    cudaFuncSetAttribute(flash_mma, cudaFuncAttributeMaxDynamicSharedMemorySize, FLASH_SMEM);

    split_all<<<(N4_TOTAL + 255) / 256, 256>>>(x, Wq, Wk, Wv, Wo);

    gemm_qkv<<<dim3(HD / 128, S_LEN / 128, 3), 256, GEMM_SMEM>>>();

    flash_mma<<<dim3(S_LEN / 128, 16), 256, FLASH_SMEM>>>(Ah, Al);

    gemm_out<<<dim3(HD / 128, S_LEN / 128), 256, GEMM_SMEM>>>(out);
}

// round 15
// speedup vs baseline: 6.5024x; 1.1376x over previous
#include <cuda_runtime.h>
#include <cuda_fp16.h>
#include <math.h>
#include <cstdint>

#define S_LEN 2048
#define HD    1024
#define ALPHA_Q 0.1803368801111601f   // 0.125 * log2(e)

// ---------------------------------------------------------------------------
// Scratch (device globals) — fp16 scheme:
//   x: hi+lo (Q proj only uses both; K/V proj use hi).  Weights: fp16.
//   Q: hi+lo.  K, V: fp16.  A: fp16 (single).
// ---------------------------------------------------------------------------
__device__ __align__(16) __half g_xh[S_LEN * HD], g_xl[S_LEN * HD];
__device__ __align__(16) __half g_wq[HD * HD], g_wk[HD * HD];
__device__ __align__(16) __half g_wv[HD * HD], g_wo[HD * HD];
__device__ __align__(16) __half g_Qh[S_LEN * HD], g_Ql[S_LEN * HD];
__device__ __align__(16) __half g_K[S_LEN * HD],  g_V[S_LEN * HD];
__device__ __align__(16) __half g_A[S_LEN * HD];

// ---------------------------------------------------------------------------
// Portable PTX helpers (sm_80-level, legal on bare sm_103)
// ---------------------------------------------------------------------------
__device__ __forceinline__ uint32_t smem_u32(const void* p) {
    uint32_t a;
    asm("{ .reg .u64 t; cvta.to.shared.u64 t, %1; cvt.u32.u64 %0, t; }"
        : "=r"(a) : "l"(p));
    return a;
}
__device__ __forceinline__ void cp_async16(uint32_t dst, const void* src) {
    asm volatile("cp.async.cg.shared.global [%0], [%1], 16;" :: "r"(dst), "l"(src));
}
__device__ __forceinline__ void cp_commit() {
    asm volatile("cp.async.commit_group;" ::: "memory");
}
template<int N> __device__ __forceinline__ void cp_wait() {
    asm volatile("cp.async.wait_group %0;" :: "n"(N) : "memory");
}
__device__ __forceinline__ void ldsm_x4(uint32_t* r, uint32_t a) {
    asm volatile("ldmatrix.sync.aligned.m8n8.x4.shared.b16 {%0,%1,%2,%3}, [%4];"
                 : "=r"(r[0]), "=r"(r[1]), "=r"(r[2]), "=r"(r[3]) : "r"(a));
}
__device__ __forceinline__ void ldsm_x4_t(uint32_t* r, uint32_t a) {
    asm volatile("ldmatrix.sync.aligned.m8n8.x4.trans.shared.b16 {%0,%1,%2,%3}, [%4];"
                 : "=r"(r[0]), "=r"(r[1]), "=r"(r[2]), "=r"(r[3]) : "r"(a));
}
__device__ __forceinline__ void mma_f16(float* c, const uint32_t* a, const uint32_t* b) {
    asm volatile(
        "mma.sync.aligned.m16n8k16.row.col.f32.f16.f16.f32 "
        "{%0,%1,%2,%3}, {%4,%5,%6,%7}, {%8,%9}, {%0,%1,%2,%3};"
        : "+f"(c[0]), "+f"(c[1]), "+f"(c[2]), "+f"(c[3])
        : "r"(a[0]), "r"(a[1]), "r"(a[2]), "r"(a[3]), "r"(b[0]), "r"(b[1]));
}
__device__ __forceinline__ float ex2(float x) {
    float r; asm("ex2.approx.f32 %0, %1;" : "=f"(r) : "f"(x)); return r;
}
// 128B-row swizzle; cb must be 16B aligned
__device__ __forceinline__ uint32_t swz(int row, int cb) {
    return (uint32_t)(row * 128 + (cb ^ ((row & 7) << 4)));
}
// pack two floats to f16x2 (x -> low half)
__device__ __forceinline__ uint32_t pack2h(float x, float y) {
    uint32_t r;
    asm("cvt.rn.f16x2.f32 %0, %1, %2;" : "=r"(r) : "f"(y), "f"(x));
    return r;
}
// two floats -> f16x2 hi + f16x2 lo (round-to-nearest split)
__device__ __forceinline__ void split2h(float x, float y, uint32_t& hi, uint32_t& lo) {
    hi = pack2h(x, y);
    __half2 h = *reinterpret_cast<__half2*>(&hi);
    float rx = x - __half2float(h.x);
    float ry = y - __half2float(h.y);
    lo = pack2h(rx, ry);
}

// ---------------------------------------------------------------------------
// Fused conversion: x -> fp16 hi/lo ; Wq/Wk/Wv/Wo -> fp16 — ONE launch.
// ---------------------------------------------------------------------------
#define N4_X 524288
#define N4_W 262144
#define N4_TOTAL (N4_X + 4 * N4_W)

__global__ void __launch_bounds__(256)
split_all(const float* __restrict__ x,  const float* __restrict__ Wq,
          const float* __restrict__ Wk, const float* __restrict__ Wv,
          const float* __restrict__ Wo)
{
    int i = blockIdx.x * blockDim.x + threadIdx.x;
    if (i >= N4_TOTAL) return;
    int j = i;
    if (j < N4_X) {
        float4 v = ((const float4*)x)[j];
        uint32_t h0, l0, h1, l1;
        split2h(v.x, v.y, h0, l0);
        split2h(v.z, v.w, h1, l1);
        ((uint32_t*)g_xh)[2 * j + 0] = h0;
        ((uint32_t*)g_xh)[2 * j + 1] = h1;
        ((uint32_t*)g_xl)[2 * j + 0] = l0;
        ((uint32_t*)g_xl)[2 * j + 1] = l1;
        return;
    }
    j -= N4_X;
    const float* in;
    __half* w;
    if (j < N4_W)      { in = Wq; w = g_wq; }
    else if ((j -= N4_W) < N4_W) { in = Wk; w = g_wk; }
    else if ((j -= N4_W) < N4_W) { in = Wv; w = g_wv; }
    else               { j -= N4_W; in = Wo; w = g_wo; }
    float4 v = ((const float4*)in)[j];
    ((uint32_t*)w)[2 * j + 0] = pack2h(v.x, v.y);
    ((uint32_t*)w)[2 * j + 1] = pack2h(v.z, v.w);
}

// ---------------------------------------------------------------------------
// Split-GEMM core: C = (Ah [+ Al]) * B^T.  Al == nullptr -> single-section.
// Block 128x128, BK=64, 8 warps, double-buffered, 2 CTAs/SM.
// ---------------------------------------------------------------------------
#define G_STAGE 49152
#define GEMM_SMEM (2 * G_STAGE)    // 98304
#define NCHUNK 16

__device__ __forceinline__ void gemm_core(
    uint32_t sb,
    const __half* Ah, const __half* Al, const __half* B,
    __half* outHi, __half* outLo, float* outF,
    float alpha, int m0, int n0)
{
    const int tid = threadIdx.x;
    const int lane = tid & 31, wid = tid >> 5;
    const int wm = wid & 3, wn = wid >> 2;

    float c[2][8][4];
#pragma unroll
    for (int mt = 0; mt < 2; mt++)
#pragma unroll
        for (int nt = 0; nt < 8; nt++)
#pragma unroll
            for (int j = 0; j < 4; j++) c[mt][nt][j] = 0.f;

    auto issue = [&](int ck, int stage) {
        size_t ko = (size_t)ck * 128;            // bytes into each 2048B row
        uint32_t dAh = sb + stage * G_STAGE;
        uint32_t dAl = dAh + 16384;
        uint32_t dB  = dAh + 32768;
#pragma unroll
        for (int i = 0; i < 4; i++) {
            int lin = tid + i * 256;
            int row = lin >> 3, cb = (lin & 7) << 4;
            size_t goA = (size_t)(m0 + row) * 2048 + ko + cb;
            cp_async16(dAh + swz(row, cb), (const char*)Ah + goA);
            if (Al) cp_async16(dAl + swz(row, cb), (const char*)Al + goA);
            cp_async16(dB + swz(row, cb),
                       (const char*)B + (size_t)(n0 + row) * 2048 + ko + cb);
        }
        cp_commit();
    };

    issue(0, 0);
    issue(1, 1);

    for (int ck = 0; ck < NCHUNK; ck++) {
        if (ck == NCHUNK - 1) cp_wait<0>(); else cp_wait<1>();
        __syncthreads();
        uint32_t aH = sb + (ck & 1) * G_STAGE;
        uint32_t aL = aH + 16384;
        uint32_t bB = aH + 32768;
#pragma unroll
        for (int kk = 0; kk < 4; kk++) {
            uint32_t afh[2][4], afl[2][4], bfr[8][2];
#pragma unroll
            for (int mt = 0; mt < 2; mt++) {
                int row = wm * 32 + mt * 16 + (lane & 15);
                int cb = kk * 32 + ((lane & 16) ? 16 : 0);
                ldsm_x4(afh[mt], aH + swz(row, cb));
                if (Al) ldsm_x4(afl[mt], aL + swz(row, cb));
            }
#pragma unroll
            for (int ng = 0; ng < 4; ng++) {
                uint32_t t[4];
                int row = wn * 64 + ng * 16 + (lane & 7) + ((lane & 16) ? 8 : 0);
                int cb = kk * 32 + ((lane & 8) ? 16 : 0);
                ldsm_x4(t, bB + swz(row, cb));
                bfr[2 * ng][0] = t[0];     bfr[2 * ng][1] = t[1];
                bfr[2 * ng + 1][0] = t[2]; bfr[2 * ng + 1][1] = t[3];
            }
#pragma unroll
            for (int mt = 0; mt < 2; mt++)
#pragma unroll
                for (int nt = 0; nt < 8; nt++) {
                    mma_f16(c[mt][nt], afh[mt], bfr[nt]);
                    if (Al) mma_f16(c[mt][nt], afl[mt], bfr[nt]);
                }
        }
        __syncthreads();
        if (ck + 2 < NCHUNK) issue(ck + 2, ck & 1);
    }

    const int gid = lane >> 2, t2 = (lane & 3) * 2;
#pragma unroll
    for (int mt = 0; mt < 2; mt++)
#pragma unroll
        for (int hh = 0; hh < 2; hh++) {
            int row = m0 + wm * 32 + mt * 16 + gid + hh * 8;
#pragma unroll
            for (int nt = 0; nt < 8; nt++) {
                int col = n0 + wn * 64 + nt * 8 + t2;
                float v0 = c[mt][nt][2 * hh] * alpha;
                float v1 = c[mt][nt][2 * hh + 1] * alpha;
                size_t idx = (size_t)row * 1024 + col;
                if (outF) {
                    *(float2*)(outF + idx) = make_float2(v0, v1);
                } else if (outLo) {
                    uint32_t hb, lb;
                    split2h(v0, v1, hb, lb);
                    ((uint32_t*)outHi)[idx >> 1] = hb;
                    ((uint32_t*)outLo)[idx >> 1] = lb;
                } else {
                    ((uint32_t*)outHi)[idx >> 1] = pack2h(v0, v1);
                }
            }
        }
}

// Fused Q/K/V projections: Q 2-term (xh+xl), K and V single-term (xh).
__global__ void __launch_bounds__(256, 2)
gemm_qkv()
{
    extern __shared__ __align__(128) char sm_g[];
    const uint32_t sb = smem_u32(sm_g);
    const int m0 = blockIdx.y * 128, n0 = blockIdx.x * 128;
    const int z = blockIdx.z;
    if (z == 0)
        gemm_core(sb, g_xh, g_xl, g_wq, g_Qh, g_Ql, nullptr, (float)ALPHA_Q, m0, n0);
    else if (z == 1)
        gemm_core(sb, g_xh, nullptr, g_wk, g_K, nullptr, nullptr, 1.0f, m0, n0);
    else
        gemm_core(sb, g_xh, nullptr, g_wv, g_V, nullptr, nullptr, 1.0f, m0, n0);
}

// Output projection: A (fp16 single) x Wo -> fp32 out.
__global__ void __launch_bounds__(256, 2)
gemm_out(float* __restrict__ out)
{
    extern __shared__ __align__(128) char sm_g[];
    const uint32_t sb = smem_u32(sm_g);
    gemm_core(sb, g_A, nullptr, g_wo, nullptr, nullptr, out, 1.0f,
              blockIdx.y * 128, blockIdx.x * 128);
}

// ---------------------------------------------------------------------------
// Flash attention, fp16 mma, double-buffered K/V, 2 CTAs/SM.
// P·V single-term; A output plain fp16.
// ---------------------------------------------------------------------------
#define SQH 0
#define SQL 16384
#define SKV0 32768
#define KV_STAGE 16384
#define OK 0
#define OV 8192
#define FLASH_SMEM (32768 + 2 * KV_STAGE)   // 65536

__global__ void __launch_bounds__(256, 2)
flash_mma(__half* __restrict__ A_)
{
    extern __shared__ __align__(128) char sm_f[];
    const uint32_t sb = smem_u32(sm_f);
    const int tid = threadIdx.x, lane = tid & 31, w = tid >> 5;
    const int h = blockIdx.y, q0 = blockIdx.x * 128;

    auto ldKV = [&](int kt) {
        uint32_t st = sb + SKV0 + (uint32_t)(kt & 1) * KV_STAGE;
        size_t kr = (size_t)kt * 64;
#pragma unroll
        for (int i = 0; i < 2; i++) {
            int lin = tid + i * 256;
            int row = lin >> 3, cb = (lin & 7) << 4;
            size_t go = (kr + row) * 2048 + (size_t)h * 128 + cb;
            uint32_t so = swz(row, cb);
            cp_async16(st + OK + so, (const char*)g_K + go);
            cp_async16(st + OV + so, (const char*)g_V + go);
        }
        cp_commit();
    };

#pragma unroll
    for (int i = 0; i < 4; i++) {
        int lin = tid + i * 256;
        int row = lin >> 3, cb = (lin & 7) << 4;
        size_t go = (size_t)(q0 + row) * 2048 + (size_t)h * 128 + cb;
        cp_async16(sb + SQH + swz(row, cb), (const char*)g_Qh + go);
        cp_async16(sb + SQL + swz(row, cb), (const char*)g_Ql + go);
    }
    cp_commit();
    ldKV(0);
    ldKV(1);

    cp_wait<2>();
    __syncthreads();

    uint32_t qh[4][4], ql[4][4];
    {
        int row = w * 16 + (lane & 15);
#pragma unroll
        for (int kk = 0; kk < 4; kk++) {
            int cb = kk * 32 + ((lane & 16) ? 16 : 0);
            ldsm_x4(qh[kk], sb + SQH + swz(row, cb));
            ldsm_x4(ql[kk], sb + SQL + swz(row, cb));
        }
    }

    float m0v = -INFINITY, m1v = -INFINITY, l0v = 0.f, l1v = 0.f;
    float o[8][4];
#pragma unroll
    for (int d = 0; d < 8; d++)
#pragma unroll
        for (int j = 0; j < 4; j++) o[d][j] = 0.f;

    for (int kt = 0; kt < 32; kt++) {
        if (kt == 31) cp_wait<0>(); else cp_wait<1>();
        __syncthreads();
        const uint32_t st = sb + SKV0 + (uint32_t)(kt & 1) * KV_STAGE;

        float c[8][4];
#pragma unroll
        for (int nt = 0; nt < 8; nt++)
#pragma unroll
            for (int j = 0; j < 4; j++) c[nt][j] = 0.f;

#pragma unroll
        for (int kk = 0; kk < 4; kk++) {
#pragma unroll
            for (int ng = 0; ng < 4; ng++) {
                uint32_t bh[4];
                int row = ng * 16 + (lane & 7) + ((lane & 16) ? 8 : 0);
                int cb = kk * 32 + ((lane & 8) ? 16 : 0);
                ldsm_x4(bh, st + OK + swz(row, cb));
                mma_f16(c[2 * ng],     qh[kk], bh);
                mma_f16(c[2 * ng],     ql[kk], bh);
                mma_f16(c[2 * ng + 1], qh[kk], bh + 2);
                mma_f16(c[2 * ng + 1], ql[kk], bh + 2);
            }
        }

        float mx0 = -INFINITY, mx1 = -INFINITY;
#pragma unroll
        for (int nt = 0; nt < 8; nt++) {
            mx0 = fmaxf(mx0, fmaxf(c[nt][0], c[nt][1]));
            mx1 = fmaxf(mx1, fmaxf(c[nt][2], c[nt][3]));
        }
        mx0 = fmaxf(mx0, __shfl_xor_sync(0xffffffffu, mx0, 1));
        mx0 = fmaxf(mx0, __shfl_xor_sync(0xffffffffu, mx0, 2));
        mx1 = fmaxf(mx1, __shfl_xor_sync(0xffffffffu, mx1, 1));
        mx1 = fmaxf(mx1, __shfl_xor_sync(0xffffffffu, mx1, 2));
        float mn0 = fmaxf(m0v, mx0), mn1 = fmaxf(m1v, mx1);
        float cor0 = ex2(m0v - mn0), cor1 = ex2(m1v - mn1);
        float rs0 = 0.f, rs1 = 0.f;
#pragma unroll
        for (int nt = 0; nt < 8; nt++) {
            c[nt][0] = ex2(c[nt][0] - mn0);
            c[nt][1] = ex2(c[nt][1] - mn0);
            c[nt][2] = ex2(c[nt][2] - mn1);
            c[nt][3] = ex2(c[nt][3] - mn1);
            rs0 += c[nt][0] + c[nt][1];
            rs1 += c[nt][2] + c[nt][3];
        }
        rs0 += __shfl_xor_sync(0xffffffffu, rs0, 1);
        rs0 += __shfl_xor_sync(0xffffffffu, rs0, 2);
        rs1 += __shfl_xor_sync(0xffffffffu, rs1, 1);
        rs1 += __shfl_xor_sync(0xffffffffu, rs1, 2);
        l0v = l0v * cor0 + rs0;
        l1v = l1v * cor1 + rs1;
        m0v = mn0; m1v = mn1;
#pragma unroll
        for (int d = 0; d < 8; d++) {
            o[d][0] *= cor0; o[d][1] *= cor0;
            o[d][2] *= cor1; o[d][3] *= cor1;
        }

        // ---- O += P V (P plain fp16; single term), V via ldmatrix.trans ----
#pragma unroll
        for (int kk = 0; kk < 4; kk++) {
            uint32_t ah[4];
            ah[0] = pack2h(c[2 * kk][0],     c[2 * kk][1]);
            ah[1] = pack2h(c[2 * kk][2],     c[2 * kk][3]);
            ah[2] = pack2h(c[2 * kk + 1][0], c[2 * kk + 1][1]);
            ah[3] = pack2h(c[2 * kk + 1][2], c[2 * kk + 1][3]);
            int row = kk * 16 + (lane & 15);
#pragma unroll
            for (int dg = 0; dg < 4; dg++) {
                uint32_t bh[4];
                int cb = dg * 32 + ((lane & 16) ? 16 : 0);
                ldsm_x4_t(bh, st + OV + swz(row, cb));
                mma_f16(o[2 * dg],     ah, bh);
                mma_f16(o[2 * dg + 1], ah, bh + 2);
            }
        }
        __syncthreads();
        if (kt + 2 < 32) ldKV(kt + 2);
    }

    // ---- epilogue: normalize, plain fp16 A, concat-head layout ----
    float inv0 = 1.f / l0v, inv1 = 1.f / l1v;
    const int gid = lane >> 2, t2 = (lane & 3) * 2;
    int r0 = q0 + w * 16 + gid;
#pragma unroll
    for (int d = 0; d < 8; d++) {
        int col = h * 64 + d * 8 + t2;
        size_t i0 = ((size_t)r0 * 1024 + col) >> 1;
        ((uint32_t*)A_)[i0] = pack2h(o[d][0] * inv0, o[d][1] * inv0);
        size_t i1 = ((size_t)(r0 + 8) * 1024 + col) >> 1;
        ((uint32_t*)A_)[i1] = pack2h(o[d][2] * inv1, o[d][3] * inv1);
    }
}

// ---------------------------------------------------------------------------
// Launch
// ---------------------------------------------------------------------------
extern "C" void kernel_launch(void* const* d_in, const int* in_sizes, int n_in,
                              void* d_out, int out_size)
{
    (void)in_sizes; (void)n_in; (void)out_size;
    const float* x  = (const float*)d_in[0];
    const float* Wq = (const float*)d_in[1];
    const float* Wk = (const float*)d_in[2];
    const float* Wv = (const float*)d_in[3];
    const float* Wo = (const float*)d_in[4];
    float* out = (float*)d_out;

    __half *A;
    cudaGetSymbolAddress((void**)&A, g_A);

    cudaFuncSetAttribute(gemm_qkv, cudaFuncAttributeMaxDynamicSharedMemorySize, GEMM_SMEM);
    cudaFuncSetAttribute(gemm_out, cudaFuncAttributeMaxDynamicSharedMemorySize, GEMM_SMEM);
    cudaFuncSetAttribute(flash_mma, cudaFuncAttributeMaxDynamicSharedMemorySize, FLASH_SMEM);

    split_all<<<(N4_TOTAL + 255) / 256, 256>>>(x, Wq, Wk, Wv, Wo);

    gemm_qkv<<<dim3(HD / 128, S_LEN / 128, 3), 256, GEMM_SMEM>>>();

    flash_mma<<<dim3(S_LEN / 128, 16), 256, FLASH_SMEM>>>(A);

    gemm_out<<<dim3(HD / 128, S_LEN / 128), 256, GEMM_SMEM>>>(out);
}

// round 16
// speedup vs baseline: 8.4232x; 1.2954x over previous
#include <cuda_runtime.h>
#include <cuda_fp16.h>
#include <math.h>
#include <cstdint>

#define S_LEN 2048
#define HD    1024
#define ALPHA_Q 0.1803368801111601f   // 0.125 * log2(e)

// ---------------------------------------------------------------------------
// Scratch (device globals) — full fp16 scheme (fp32 accum everywhere).
// ---------------------------------------------------------------------------
__device__ __align__(16) __half g_x[S_LEN * HD];
__device__ __align__(16) __half g_wq[HD * HD], g_wk[HD * HD];
__device__ __align__(16) __half g_wv[HD * HD], g_wo[HD * HD];
__device__ __align__(16) __half g_Q[S_LEN * HD];
__device__ __align__(16) __half g_K[S_LEN * HD],  g_V[S_LEN * HD];
__device__ __align__(16) __half g_A[S_LEN * HD];

// ---------------------------------------------------------------------------
// Portable PTX helpers (sm_80-level, legal on bare sm_103)
// ---------------------------------------------------------------------------
__device__ __forceinline__ uint32_t smem_u32(const void* p) {
    uint32_t a;
    asm("{ .reg .u64 t; cvta.to.shared.u64 t, %1; cvt.u32.u64 %0, t; }"
        : "=r"(a) : "l"(p));
    return a;
}
__device__ __forceinline__ void cp_async16(uint32_t dst, const void* src) {
    asm volatile("cp.async.cg.shared.global [%0], [%1], 16;" :: "r"(dst), "l"(src));
}
__device__ __forceinline__ void cp_commit() {
    asm volatile("cp.async.commit_group;" ::: "memory");
}
template<int N> __device__ __forceinline__ void cp_wait() {
    asm volatile("cp.async.wait_group %0;" :: "n"(N) : "memory");
}
__device__ __forceinline__ void ldsm_x4(uint32_t* r, uint32_t a) {
    asm volatile("ldmatrix.sync.aligned.m8n8.x4.shared.b16 {%0,%1,%2,%3}, [%4];"
                 : "=r"(r[0]), "=r"(r[1]), "=r"(r[2]), "=r"(r[3]) : "r"(a));
}
__device__ __forceinline__ void ldsm_x4_t(uint32_t* r, uint32_t a) {
    asm volatile("ldmatrix.sync.aligned.m8n8.x4.trans.shared.b16 {%0,%1,%2,%3}, [%4];"
                 : "=r"(r[0]), "=r"(r[1]), "=r"(r[2]), "=r"(r[3]) : "r"(a));
}
__device__ __forceinline__ void mma_f16(float* c, const uint32_t* a, const uint32_t* b) {
    asm volatile(
        "mma.sync.aligned.m16n8k16.row.col.f32.f16.f16.f32 "
        "{%0,%1,%2,%3}, {%4,%5,%6,%7}, {%8,%9}, {%0,%1,%2,%3};"
        : "+f"(c[0]), "+f"(c[1]), "+f"(c[2]), "+f"(c[3])
        : "r"(a[0]), "r"(a[1]), "r"(a[2]), "r"(a[3]), "r"(b[0]), "r"(b[1]));
}
__device__ __forceinline__ float ex2(float x) {
    float r; asm("ex2.approx.f32 %0, %1;" : "=f"(r) : "f"(x)); return r;
}
// 128B-row swizzle; cb must be 16B aligned
__device__ __forceinline__ uint32_t swz(int row, int cb) {
    return (uint32_t)(row * 128 + (cb ^ ((row & 7) << 4)));
}
// pack two floats to f16x2 (x -> low half)
__device__ __forceinline__ uint32_t pack2h(float x, float y) {
    uint32_t r;
    asm("cvt.rn.f16x2.f32 %0, %1, %2;" : "=r"(r) : "f"(y), "f"(x));
    return r;
}

// ---------------------------------------------------------------------------
// Fused conversion: x, Wq, Wk, Wv, Wo -> fp16 — ONE launch.
// ---------------------------------------------------------------------------
#define N4_X 524288
#define N4_W 262144
#define N4_TOTAL (N4_X + 4 * N4_W)

__global__ void __launch_bounds__(256)
split_all(const float* __restrict__ x,  const float* __restrict__ Wq,
          const float* __restrict__ Wk, const float* __restrict__ Wv,
          const float* __restrict__ Wo)
{
    int i = blockIdx.x * blockDim.x + threadIdx.x;
    if (i >= N4_TOTAL) return;
    int j = i;
    const float* in;
    __half* w;
    if (j < N4_X)                 { in = x;  w = g_x; }
    else if ((j -= N4_X) < N4_W)  { in = Wq; w = g_wq; }
    else if ((j -= N4_W) < N4_W)  { in = Wk; w = g_wk; }
    else if ((j -= N4_W) < N4_W)  { in = Wv; w = g_wv; }
    else                          { j -= N4_W; in = Wo; w = g_wo; }
    float4 v = ((const float4*)in)[j];
    ((uint32_t*)w)[2 * j + 0] = pack2h(v.x, v.y);
    ((uint32_t*)w)[2 * j + 1] = pack2h(v.z, v.w);
}

// ---------------------------------------------------------------------------
// GEMM core: C[2048,1024] = A[2048,1024] * B[1024,1024]^T, fp16 in, fp32 acc.
// Block 128x128, BK=64, 8 warps, double-buffered, 2 CTAs/SM.
// ---------------------------------------------------------------------------
#define G_STAGE 32768            // A 16KB + B 16KB
#define GEMM_SMEM (2 * G_STAGE)  // 65536
#define NCHUNK 16

__device__ __forceinline__ void gemm_core(
    uint32_t sb, const __half* A, const __half* B,
    __half* outH, float* outF, float alpha, int m0, int n0)
{
    const int tid = threadIdx.x;
    const int lane = tid & 31, wid = tid >> 5;
    const int wm = wid & 3, wn = wid >> 2;

    float c[2][8][4];
#pragma unroll
    for (int mt = 0; mt < 2; mt++)
#pragma unroll
        for (int nt = 0; nt < 8; nt++)
#pragma unroll
            for (int j = 0; j < 4; j++) c[mt][nt][j] = 0.f;

    auto issue = [&](int ck, int stage) {
        size_t ko = (size_t)ck * 128;
        uint32_t dA = sb + stage * G_STAGE;
        uint32_t dB = dA + 16384;
#pragma unroll
        for (int i = 0; i < 4; i++) {
            int lin = tid + i * 256;
            int row = lin >> 3, cb = (lin & 7) << 4;
            cp_async16(dA + swz(row, cb),
                       (const char*)A + (size_t)(m0 + row) * 2048 + ko + cb);
            cp_async16(dB + swz(row, cb),
                       (const char*)B + (size_t)(n0 + row) * 2048 + ko + cb);
        }
        cp_commit();
    };

    issue(0, 0);
    issue(1, 1);

    for (int ck = 0; ck < NCHUNK; ck++) {
        if (ck == NCHUNK - 1) cp_wait<0>(); else cp_wait<1>();
        __syncthreads();
        uint32_t aB = sb + (ck & 1) * G_STAGE;
        uint32_t bB = aB + 16384;
#pragma unroll
        for (int kk = 0; kk < 4; kk++) {
            uint32_t afr[2][4], bfr[8][2];
#pragma unroll
            for (int mt = 0; mt < 2; mt++) {
                int row = wm * 32 + mt * 16 + (lane & 15);
                int cb = kk * 32 + ((lane & 16) ? 16 : 0);
                ldsm_x4(afr[mt], aB + swz(row, cb));
            }
#pragma unroll
            for (int ng = 0; ng < 4; ng++) {
                uint32_t t[4];
                int row = wn * 64 + ng * 16 + (lane & 7) + ((lane & 16) ? 8 : 0);
                int cb = kk * 32 + ((lane & 8) ? 16 : 0);
                ldsm_x4(t, bB + swz(row, cb));
                bfr[2 * ng][0] = t[0];     bfr[2 * ng][1] = t[1];
                bfr[2 * ng + 1][0] = t[2]; bfr[2 * ng + 1][1] = t[3];
            }
#pragma unroll
            for (int mt = 0; mt < 2; mt++)
#pragma unroll
                for (int nt = 0; nt < 8; nt++)
                    mma_f16(c[mt][nt], afr[mt], bfr[nt]);
        }
        __syncthreads();
        if (ck + 2 < NCHUNK) issue(ck + 2, ck & 1);
    }

    const int gid = lane >> 2, t2 = (lane & 3) * 2;
#pragma unroll
    for (int mt = 0; mt < 2; mt++)
#pragma unroll
        for (int hh = 0; hh < 2; hh++) {
            int row = m0 + wm * 32 + mt * 16 + gid + hh * 8;
#pragma unroll
            for (int nt = 0; nt < 8; nt++) {
                int col = n0 + wn * 64 + nt * 8 + t2;
                float v0 = c[mt][nt][2 * hh] * alpha;
                float v1 = c[mt][nt][2 * hh + 1] * alpha;
                size_t idx = (size_t)row * 1024 + col;
                if (outF) *(float2*)(outF + idx) = make_float2(v0, v1);
                else      ((uint32_t*)outH)[idx >> 1] = pack2h(v0, v1);
            }
        }
}

// Fused Q/K/V projections (all single-term fp16).
__global__ void __launch_bounds__(256, 2)
gemm_qkv()
{
    extern __shared__ __align__(128) char sm_g[];
    const uint32_t sb = smem_u32(sm_g);
    const int m0 = blockIdx.y * 128, n0 = blockIdx.x * 128;
    const int z = blockIdx.z;
    if (z == 0)
        gemm_core(sb, g_x, g_wq, g_Q, nullptr, (float)ALPHA_Q, m0, n0);
    else if (z == 1)
        gemm_core(sb, g_x, g_wk, g_K, nullptr, 1.0f, m0, n0);
    else
        gemm_core(sb, g_x, g_wv, g_V, nullptr, 1.0f, m0, n0);
}

// Output projection: A x Wo -> fp32 out.
__global__ void __launch_bounds__(256, 2)
gemm_out(float* __restrict__ out)
{
    extern __shared__ __align__(128) char sm_g[];
    const uint32_t sb = smem_u32(sm_g);
    gemm_core(sb, g_A, g_wo, nullptr, out, 1.0f,
              blockIdx.y * 128, blockIdx.x * 128);
}

// ---------------------------------------------------------------------------
// Flash attention, plain fp16 mma, double-buffered K/V, 2 CTAs/SM.
// smem: Q 16KB @0; stages @16384: {K 8K, V 8K} x2.  Total 48KB.
// ---------------------------------------------------------------------------
#define SQ 0
#define SKV0 16384
#define KV_STAGE 16384
#define OK 0
#define OV 8192
#define FLASH_SMEM (16384 + 2 * KV_STAGE)   // 49152

__global__ void __launch_bounds__(256, 2)
flash_mma(__half* __restrict__ A_)
{
    extern __shared__ __align__(128) char sm_f[];
    const uint32_t sb = smem_u32(sm_f);
    const int tid = threadIdx.x, lane = tid & 31, w = tid >> 5;
    const int h = blockIdx.y, q0 = blockIdx.x * 128;

    auto ldKV = [&](int kt) {
        uint32_t st = sb + SKV0 + (uint32_t)(kt & 1) * KV_STAGE;
        size_t kr = (size_t)kt * 64;
#pragma unroll
        for (int i = 0; i < 2; i++) {
            int lin = tid + i * 256;
            int row = lin >> 3, cb = (lin & 7) << 4;
            size_t go = (kr + row) * 2048 + (size_t)h * 128 + cb;
            uint32_t so = swz(row, cb);
            cp_async16(st + OK + so, (const char*)g_K + go);
            cp_async16(st + OV + so, (const char*)g_V + go);
        }
        cp_commit();
    };

    // Q tile: 128 rows x 128B
#pragma unroll
    for (int i = 0; i < 2; i++) {
        int lin = tid + i * 256;
        int row = lin >> 2, cb = (lin & 3) << 5;    // 4 threads x 32B per row
        size_t go = (size_t)(q0 + row) * 2048 + (size_t)h * 128 + cb;
        cp_async16(sb + SQ + swz(row, cb), (const char*)g_Q + go);
        cp_async16(sb + SQ + swz(row, cb + 16), (const char*)g_Q + go + 16);
    }
    cp_commit();
    ldKV(0);
    ldKV(1);

    cp_wait<2>();
    __syncthreads();

    // Persistent Q fragments
    uint32_t qf[4][4];
    {
        int row = w * 16 + (lane & 15);
#pragma unroll
        for (int kk = 0; kk < 4; kk++) {
            int cb = kk * 32 + ((lane & 16) ? 16 : 0);
            ldsm_x4(qf[kk], sb + SQ + swz(row, cb));
        }
    }

    float m0v = -INFINITY, m1v = -INFINITY, l0v = 0.f, l1v = 0.f;
    float o[8][4];
#pragma unroll
    for (int d = 0; d < 8; d++)
#pragma unroll
        for (int j = 0; j < 4; j++) o[d][j] = 0.f;

    for (int kt = 0; kt < 32; kt++) {
        if (kt == 31) cp_wait<0>(); else cp_wait<1>();
        __syncthreads();
        const uint32_t st = sb + SKV0 + (uint32_t)(kt & 1) * KV_STAGE;

        // ---- S = Q K^T ----
        float c[8][4];
#pragma unroll
        for (int nt = 0; nt < 8; nt++)
#pragma unroll
            for (int j = 0; j < 4; j++) c[nt][j] = 0.f;

#pragma unroll
        for (int kk = 0; kk < 4; kk++) {
#pragma unroll
            for (int ng = 0; ng < 4; ng++) {
                uint32_t bh[4];
                int row = ng * 16 + (lane & 7) + ((lane & 16) ? 8 : 0);
                int cb = kk * 32 + ((lane & 8) ? 16 : 0);
                ldsm_x4(bh, st + OK + swz(row, cb));
                mma_f16(c[2 * ng],     qf[kk], bh);
                mma_f16(c[2 * ng + 1], qf[kk], bh + 2);
            }
        }

        // ---- online softmax (rows gid and gid+8) ----
        float mx0 = -INFINITY, mx1 = -INFINITY;
#pragma unroll
        for (int nt = 0; nt < 8; nt++) {
            mx0 = fmaxf(mx0, fmaxf(c[nt][0], c[nt][1]));
            mx1 = fmaxf(mx1, fmaxf(c[nt][2], c[nt][3]));
        }
        mx0 = fmaxf(mx0, __shfl_xor_sync(0xffffffffu, mx0, 1));
        mx0 = fmaxf(mx0, __shfl_xor_sync(0xffffffffu, mx0, 2));
        mx1 = fmaxf(mx1, __shfl_xor_sync(0xffffffffu, mx1, 1));
        mx1 = fmaxf(mx1, __shfl_xor_sync(0xffffffffu, mx1, 2));
        float mn0 = fmaxf(m0v, mx0), mn1 = fmaxf(m1v, mx1);
        float cor0 = ex2(m0v - mn0), cor1 = ex2(m1v - mn1);
        float rs0 = 0.f, rs1 = 0.f;
#pragma unroll
        for (int nt = 0; nt < 8; nt++) {
            c[nt][0] = ex2(c[nt][0] - mn0);
            c[nt][1] = ex2(c[nt][1] - mn0);
            c[nt][2] = ex2(c[nt][2] - mn1);
            c[nt][3] = ex2(c[nt][3] - mn1);
            rs0 += c[nt][0] + c[nt][1];
            rs1 += c[nt][2] + c[nt][3];
        }
        rs0 += __shfl_xor_sync(0xffffffffu, rs0, 1);
        rs0 += __shfl_xor_sync(0xffffffffu, rs0, 2);
        rs1 += __shfl_xor_sync(0xffffffffu, rs1, 1);
        rs1 += __shfl_xor_sync(0xffffffffu, rs1, 2);
        l0v = l0v * cor0 + rs0;
        l1v = l1v * cor1 + rs1;
        m0v = mn0; m1v = mn1;
#pragma unroll
        for (int d = 0; d < 8; d++) {
            o[d][0] *= cor0; o[d][1] *= cor0;
            o[d][2] *= cor1; o[d][3] *= cor1;
        }

        // ---- O += P V (P plain fp16), V via ldmatrix.trans ----
#pragma unroll
        for (int kk = 0; kk < 4; kk++) {
            uint32_t ah[4];
            ah[0] = pack2h(c[2 * kk][0],     c[2 * kk][1]);
            ah[1] = pack2h(c[2 * kk][2],     c[2 * kk][3]);
            ah[2] = pack2h(c[2 * kk + 1][0], c[2 * kk + 1][1]);
            ah[3] = pack2h(c[2 * kk + 1][2], c[2 * kk + 1][3]);
            int row = kk * 16 + (lane & 15);
#pragma unroll
            for (int dg = 0; dg < 4; dg++) {
                uint32_t bh[4];
                int cb = dg * 32 + ((lane & 16) ? 16 : 0);
                ldsm_x4_t(bh, st + OV + swz(row, cb));
                mma_f16(o[2 * dg],     ah, bh);
                mma_f16(o[2 * dg + 1], ah, bh + 2);
            }
        }
        __syncthreads();
        if (kt + 2 < 32) ldKV(kt + 2);
    }

    // ---- epilogue: normalize, plain fp16 A, concat-head layout ----
    float inv0 = 1.f / l0v, inv1 = 1.f / l1v;
    const int gid = lane >> 2, t2 = (lane & 3) * 2;
    int r0 = q0 + w * 16 + gid;
#pragma unroll
    for (int d = 0; d < 8; d++) {
        int col = h * 64 + d * 8 + t2;
        size_t i0 = ((size_t)r0 * 1024 + col) >> 1;
        ((uint32_t*)A_)[i0] = pack2h(o[d][0] * inv0, o[d][1] * inv0);
        size_t i1 = ((size_t)(r0 + 8) * 1024 + col) >> 1;
        ((uint32_t*)A_)[i1] = pack2h(o[d][2] * inv1, o[d][3] * inv1);
    }
}

// ---------------------------------------------------------------------------
// Launch
// ---------------------------------------------------------------------------
extern "C" void kernel_launch(void* const* d_in, const int* in_sizes, int n_in,
                              void* d_out, int out_size)
{
    (void)in_sizes; (void)n_in; (void)out_size;
    const float* x  = (const float*)d_in[0];
    const float* Wq = (const float*)d_in[1];
    const float* Wk = (const float*)d_in[2];
    const float* Wv = (const float*)d_in[3];
    const float* Wo = (const float*)d_in[4];
    float* out = (float*)d_out;

    __half *A;
    cudaGetSymbolAddress((void**)&A, g_A);

    cudaFuncSetAttribute(gemm_qkv, cudaFuncAttributeMaxDynamicSharedMemorySize, GEMM_SMEM);
    cudaFuncSetAttribute(gemm_out, cudaFuncAttributeMaxDynamicSharedMemorySize, GEMM_SMEM);
    cudaFuncSetAttribute(flash_mma, cudaFuncAttributeMaxDynamicSharedMemorySize, FLASH_SMEM);

    split_all<<<(N4_TOTAL + 255) / 256, 256>>>(x, Wq, Wk, Wv, Wo);

    gemm_qkv<<<dim3(HD / 128, S_LEN / 128, 3), 256, GEMM_SMEM>>>();

    flash_mma<<<dim3(S_LEN / 128, 16), 256, FLASH_SMEM>>>(A);

    gemm_out<<<dim3(HD / 128, S_LEN / 128), 256, GEMM_SMEM>>>(out);
}